// round 10
// baseline (speedup 1.0000x reference)
#include <cuda_runtime.h>
#include <cuda_bf16.h>
#include <math.h>
#include <stdint.h>

// ---------------- problem constants ----------------
#define B        128
#define TV       256
#define TS       40
#define VIN      1024
#define VHID     512
#define SIN      300
#define SHID     256
#define NCAT     2624
#define NFEAT    1024
#define LCROSS   512
#define NLOC     64

#define VF_ELEMS   ((size_t)B*TV*2*VHID)
#define SF_ELEMS   ((size_t)B*2*SHID)

// ---------------- scratch (__device__ globals) ----------------
__device__ float g_xp_v[(size_t)B*TV*3072];
__device__ float g_xp_s[(size_t)B*TS*1536];
__device__ float g_h_v[2*2*B*VHID];             // double buffered
__device__ float g_h_s[2*2*B*SHID];
__device__ uint32_t g_wpkhi_v[2*1536*256];      // [d][col'][k2] packed bf16x2
__device__ uint32_t g_wpklo_v[2*1536*256];
__device__ uint32_t g_wpkhi_s[2*768*128];
__device__ uint32_t g_wpklo_s[2*768*128];
__device__ float g_words[(size_t)B*TS*2*SHID];
__device__ float g_lmean[B*1024];
__device__ float g_rmean[B*1024];
__device__ float g_cat[B*NCAT];
__device__ float g_sproj[B*LCROSS];
__device__ int   g_perm_v[B], g_lenp_v[B];
__device__ int   g_perm_s[B], g_lenp_s[B];
__device__ int   g_cnt_v[TV], g_cnt_s[TS];
__device__ unsigned g_slots_v[256];
__device__ unsigned g_slots_s[64];
__device__ unsigned g_release[2];

// ---------------- numeric helpers ----------------
__device__ __forceinline__ void mma_bf16(float* d, const uint32_t* a, const uint32_t* b) {
    asm volatile(
        "mma.sync.aligned.m16n8k16.row.col.f32.bf16.bf16.f32 "
        "{%0,%1,%2,%3}, {%4,%5,%6,%7}, {%8,%9}, {%0,%1,%2,%3};"
        : "+f"(d[0]), "+f"(d[1]), "+f"(d[2]), "+f"(d[3])
        : "r"(a[0]), "r"(a[1]), "r"(a[2]), "r"(a[3]), "r"(b[0]), "r"(b[1]));
}
__device__ __forceinline__ void ldsm_x4(uint32_t* r, uint32_t saddr) {
    asm volatile("ldmatrix.sync.aligned.m8n8.x4.shared.b16 {%0,%1,%2,%3}, [%4];"
                 : "=r"(r[0]), "=r"(r[1]), "=r"(r[2]), "=r"(r[3]) : "r"(saddr));
}
__device__ __forceinline__ void ldsm_x2(uint32_t* r, uint32_t saddr) {
    asm volatile("ldmatrix.sync.aligned.m8n8.x2.shared.b16 {%0,%1}, [%2];"
                 : "=r"(r[0]), "=r"(r[1]) : "r"(saddr));
}
__device__ __forceinline__ uint32_t bfpack(__nv_bfloat16 lo, __nv_bfloat16 hi) {
    uint32_t l = __bfloat16_as_ushort(lo);
    uint32_t h = __bfloat16_as_ushort(hi);
    return l | (h << 16);
}
__device__ __forceinline__ void bfsplit2(float x0, float x1,
                                         uint32_t& hi, uint32_t& lo) {
    __nv_bfloat16 h0 = __float2bfloat16_rn(x0);
    __nv_bfloat16 h1 = __float2bfloat16_rn(x1);
    hi = bfpack(h0, h1);
    __nv_bfloat16 l0 = __float2bfloat16_rn(x0 - __bfloat162float(h0));
    __nv_bfloat16 l1 = __float2bfloat16_rn(x1 - __bfloat162float(h1));
    lo = bfpack(l0, l1);
}
__device__ __forceinline__ float4 ld_guard4(const float* p, int kg, int K) {
    if (kg + 4 <= K) return *(const float4*)p;
    float4 v;
    v.x = (kg     < K) ? p[0] : 0.f;
    v.y = (kg + 1 < K) ? p[1] : 0.f;
    v.z = (kg + 2 < K) ? p[2] : 0.f;
    v.w = (kg + 3 < K) ? p[3] : 0.f;
    return v;
}
__device__ __forceinline__ float fast_sigmoid(float x) {
    return __fdividef(1.f, 1.f + __expf(-x));
}
__device__ __forceinline__ float fast_tanh(float x) {
    return __fdividef(2.f, 1.f + __expf(-2.f * x)) - 1.f;
}

// ---------------- init ----------------
__global__ void sort_init_kernel(const int* __restrict__ v_len,
                                 const int* __restrict__ lens,
                                 int* pv, int* lv, int* ps, int* ls,
                                 int* cv, int* cs,
                                 unsigned* sv, unsigned* ss, unsigned* rel)
{
    int i = threadIdx.x;                 // 128 threads
    sv[i] = 0u; sv[i + 128] = 0u;
    if (i < 64) ss[i] = 0u;
    if (i < 2)  rel[i] = 0u;

    int a = v_len[i], rank = 0;
    for (int j = 0; j < B; j++) {
        int c = v_len[j];
        rank += (c > a) || (c == a && j < i);
    }
    pv[rank] = i; lv[rank] = a;
    a = lens[i]; rank = 0;
    for (int j = 0; j < B; j++) {
        int c = lens[j];
        rank += (c > a) || (c == a && j < i);
    }
    ps[rank] = i; ls[rank] = a;

    for (int t = i; t < TV; t += 128) {
        int c = 0;
        for (int j = 0; j < B; j++) c += (v_len[j] > t);
        cv[t] = c;
    }
    for (int t = i; t < TS; t += 128) {
        int c = 0;
        for (int j = 0; j < B; j++) c += (lens[j] > t);
        cs[t] = c;
    }
}

__global__ void zero_h_kernel(float* hv, float* hs) {
    int i = blockIdx.x * blockDim.x + threadIdx.x;
    if (i < 2*2*B*VHID) hv[i] = 0.f;
    if (i < 2*2*B*SHID) hs[i] = 0.f;
}

__global__ void zero_out_kernel(float4* p, int n4) {
    int i = blockIdx.x * blockDim.x + threadIdx.x;
    if (i < n4) p[i] = make_float4(0.f, 0.f, 0.f, 0.f);
}

// Pre-pack W_hh into bf16 hi/lo, gate-interleaved fragment layout.
// col' = jb*48 + tri*24 + g*8 + jn  maps to original col = g*H + jb*16 + tri*8 + jn.
__global__ void prep_wpk(const float* __restrict__ w, uint32_t* __restrict__ hi,
                         uint32_t* __restrict__ lo, int H)
{
    const int K2 = H / 2;
    const int G3 = 3 * H;
    int idx = blockIdx.x * blockDim.x + threadIdx.x;
    if (idx >= 2 * G3 * K2) return;
    int k2 = idx % K2;
    int c  = (idx / K2) % G3;
    int d  = idx / (K2 * G3);
    int jb  = c / 48;
    int rem = c % 48;
    int tri = rem / 24;
    int g   = (rem % 24) / 8;
    int jn  = rem % 8;
    int col = g * H + jb * 16 + tri * 8 + jn;
    const float* wp = w + ((size_t)d * G3 + col) * H + 2 * k2;
    uint32_t h, l;
    bfsplit2(wp[0], wp[1], h, l);
    hi[idx] = h;
    lo[idx] = l;
}

// ---------------- 3xBF16 tensor-core GEMM with ldmatrix fragments ----------
#define GEMM_SMEM (4 * 2 * 128 * 12 * 4)     // 49152 B
__global__ __launch_bounds__(256, 2) void gemm_bf16x3(
    const float* __restrict__ A, const float* __restrict__ W,
    const float* __restrict__ bias, float* __restrict__ C,
    int M, int N, int K, const int* __restrict__ lens, int T)
{
    extern __shared__ uint32_t dsm[];
    const int AH = 0, AL = 2*128*12, WH = 2*AL, WL = 3*AL;
    __shared__ int s_any;

    const int n0 = blockIdx.x * 128;
    const int m0 = blockIdx.y * 128;
    const int tid = threadIdx.x;

    if (lens) {
        if (tid == 0) {
            int any = 0;
            for (int r = 0; r < 128; r++) {
                int row = m0 + r;
                if (row % T < lens[row / T]) { any = 1; break; }
            }
            s_any = any;
        }
        __syncthreads();
        if (!s_any) return;
    }

    const int wid  = tid / 32, lane = tid % 32;
    const int wm   = (wid / 4) * 64;
    const int wn   = (wid % 4) * 32;
    const int gid  = lane >> 2, tig = lane & 3;
    const int quad = lane >> 3, lrow = lane & 7;
    const int arow = ((quad & 1) << 3) + lrow;
    const int ak2  = (quad >> 1) * 4;
    const int wrow = ((quad >> 1) << 3) + lrow;
    const int wk2  = (quad & 1) * 4;
    const uint32_t sbase = (uint32_t)__cvta_generic_to_shared(dsm);
    const int niter = (K + 15) >> 4;

    const int c0r = tid >> 2,          c0k = (tid & 3) * 4;
    const int c1r = (tid + 256) >> 2,  c1k = ((tid + 256) & 3) * 4;

    float acc[4][4][4];
#pragma unroll
    for (int i = 0; i < 4; i++)
#pragma unroll
        for (int j = 0; j < 4; j++)
#pragma unroll
            for (int c = 0; c < 4; c++) acc[i][j][c] = 0.f;

    float4 ra0, ra1, rw0, rw1;
    ra0 = ld_guard4(A + (size_t)(m0 + c0r) * K + c0k, c0k, K);
    ra1 = ld_guard4(A + (size_t)(m0 + c1r) * K + c1k, c1k, K);
    rw0 = ld_guard4(W + (size_t)(n0 + c0r) * K + c0k, c0k, K);
    rw1 = ld_guard4(W + (size_t)(n0 + c1r) * K + c1k, c1k, K);

    for (int kt = 0; kt < niter; kt++) {
        const int buf = kt & 1;
        const int bo = buf * 128;
        {
            uint32_t h, l;
            int k2 = c0k >> 1;
            int r0i = (bo + c0r) * 12, r1i = (bo + c1r) * 12;
            bfsplit2(ra0.x, ra0.y, h, l); dsm[AH + r0i + k2] = h;     dsm[AL + r0i + k2] = l;
            bfsplit2(ra0.z, ra0.w, h, l); dsm[AH + r0i + k2 + 1] = h; dsm[AL + r0i + k2 + 1] = l;
            bfsplit2(rw0.x, rw0.y, h, l); dsm[WH + r0i + k2] = h;     dsm[WL + r0i + k2] = l;
            bfsplit2(rw0.z, rw0.w, h, l); dsm[WH + r0i + k2 + 1] = h; dsm[WL + r0i + k2 + 1] = l;
            k2 = c1k >> 1;
            bfsplit2(ra1.x, ra1.y, h, l); dsm[AH + r1i + k2] = h;     dsm[AL + r1i + k2] = l;
            bfsplit2(ra1.z, ra1.w, h, l); dsm[AH + r1i + k2 + 1] = h; dsm[AL + r1i + k2 + 1] = l;
            bfsplit2(rw1.x, rw1.y, h, l); dsm[WH + r1i + k2] = h;     dsm[WL + r1i + k2] = l;
            bfsplit2(rw1.z, rw1.w, h, l); dsm[WH + r1i + k2 + 1] = h; dsm[WL + r1i + k2 + 1] = l;
        }
        __syncthreads();

        if (kt + 1 < niter) {
            const int kg = (kt + 1) * 16;
            ra0 = ld_guard4(A + (size_t)(m0 + c0r) * K + kg + c0k, kg + c0k, K);
            ra1 = ld_guard4(A + (size_t)(m0 + c1r) * K + kg + c1k, kg + c1k, K);
            rw0 = ld_guard4(W + (size_t)(n0 + c0r) * K + kg + c0k, kg + c0k, K);
            rw1 = ld_guard4(W + (size_t)(n0 + c1r) * K + kg + c1k, kg + c1k, K);
        }

        uint32_t bh[4][2], bl[4][2];
#pragma unroll
        for (int jp = 0; jp < 2; jp++) {
            uint32_t r[4];
            uint32_t a = sbase + (WH + (bo + wn + jp * 16 + wrow) * 12 + wk2) * 4;
            ldsm_x4(r, a);
            bh[jp*2][0] = r[0]; bh[jp*2][1] = r[1];
            bh[jp*2+1][0] = r[2]; bh[jp*2+1][1] = r[3];
            ldsm_x4(r, a + (WL - WH) * 4);
            bl[jp*2][0] = r[0]; bl[jp*2][1] = r[1];
            bl[jp*2+1][0] = r[2]; bl[jp*2+1][1] = r[3];
        }
#pragma unroll
        for (int mi = 0; mi < 4; mi++) {
            uint32_t ah[4], al[4];
            uint32_t a = sbase + (AH + (bo + wm + mi * 16 + arow) * 12 + ak2) * 4;
            ldsm_x4(ah, a);
            ldsm_x4(al, a + (AL - AH) * 4);
#pragma unroll
            for (int j = 0; j < 4; j++) {
                mma_bf16(acc[mi][j], ah, bh[j]);
                mma_bf16(acc[mi][j], al, bh[j]);
                mma_bf16(acc[mi][j], ah, bl[j]);
            }
        }
    }

#pragma unroll
    for (int i = 0; i < 4; i++) {
#pragma unroll
        for (int j = 0; j < 4; j++) {
            int col = n0 + wn + j * 8 + tig * 2;
            float b0 = bias[col], b1 = bias[col + 1];
            int r0g = m0 + wm + i * 16 + gid;
            *(float2*)&C[(size_t)r0g * N + col] =
                make_float2(acc[i][j][0] + b0, acc[i][j][1] + b1);
            *(float2*)&C[(size_t)(r0g + 8) * N + col] =
                make_float2(acc[i][j][2] + b0, acc[i][j][3] + b1);
        }
    }
}

// ---------------- spread-address dissemination grid barrier ----------------
__device__ __forceinline__ void grid_sync_fast(
    volatile unsigned* slots, volatile unsigned* release,
    int ncta, unsigned* gen)
{
    const unsigned target = *gen + 1u;
    __syncthreads();
    if (blockIdx.x == 0) {
        for (int c = threadIdx.x; c < ncta; c += blockDim.x) {
            if (c == 0) continue;
            while (slots[c] < target) { }
        }
        __syncthreads();
        if (threadIdx.x == 0) {
            __threadfence();
            *release = target;
        }
        __syncthreads();
    } else {
        if (threadIdx.x == 0) {
            __threadfence();
            slots[blockIdx.x] = target;
            while (*release < target) { }
            __threadfence();
        }
        __syncthreads();
    }
    *gen = target;
}

// ---------------- persistent GRU v2: gate-interleaved, no partials ---------
// CTA = (dir, 64-row block, 16 h-cols = 48 gate-cols interleaved per 8j).
// Full-K bf16x3 MMA, gate math in registers, ONE grid barrier per step.
// smem u32 layout:
//   HsmH[2][4][64*12]  off 0      (6144)
//   HsmL               off 6144
//   WsmH[2][4][48*12]  off 12288  (4608)
//   WsmL               off 16896
#define GRU2_SMEM (21504 * 4)
template<int H, int T, int JB, int NCTA>
__global__ __launch_bounds__(256, 2) void gru_v2(
    const float* __restrict__ xp,
    const uint32_t* __restrict__ wpkhi, const uint32_t* __restrict__ wpklo,
    const float* __restrict__ b_hh, float* __restrict__ hbuf,
    float* __restrict__ out,
    const int* __restrict__ perm, const int* __restrict__ cnt,
    unsigned* __restrict__ slots, unsigned* __restrict__ release)
{
    constexpr int K2  = H / 2;
    constexpr int KCH = H / 64;
    constexpr int G3  = 3 * H;
    extern __shared__ uint32_t sm[];
    const int HS_H = 0, HS_L = 6144, WS_H = 12288, WS_L = 16896;

    const int cta = blockIdx.x;
    const int d    = cta / (2 * JB);
    const int rowb = (cta % (2 * JB)) / JB;
    const int jb   = cta % JB;
    const int r0   = rowb * 64;
    const int c0p  = jb * 48;              // col' base within dir
    const int jcol0 = jb * 16;

    const int tid  = threadIdx.x;
    const int wid  = tid / 32, lane = tid % 32;
    const int wr   = wid >> 1, wc = wid & 1;
    const int gid  = lane >> 2, tig = lane & 3;
    const int quad = lane >> 3, lrow = lane & 7;
    const int arow = ((quad & 1) << 3) + lrow;
    const int ak2  = (quad >> 1) << 2;
    const int wrow = ((quad >> 1) << 3) + lrow;
    const int wk2  = (quad & 1) << 2;
    const int x2row = lane & 7;
    const int x2k2  = ((lane >> 3) & 1) << 2;
    const uint32_t sbase = (uint32_t)__cvta_generic_to_shared(sm);

    const uint32_t* whbase = wpkhi + ((size_t)d * G3 + c0p) * K2;
    const uint32_t* wlbase = wpklo + ((size_t)d * G3 + c0p) * K2;

    float* hcur = hbuf;
    float* hnxt = hbuf + 2 * B * H;
    unsigned gen = 0;

    auto stage = [&](int buf, int kc, const float* hc) {
        // h: 64 rows x 64 k fp32 -> hi/lo packed
        for (int e = tid; e < 64 * 16; e += 256) {
            int row = e >> 4, k4 = e & 15;
            int slab = k4 >> 2, k2s = (k4 & 3) * 2;
            float4 v = __ldcg((const float4*)&hc[((size_t)d * B + r0 + row) * H + kc * 64 + k4 * 4]);
            uint32_t h0, l0, h1, l1;
            bfsplit2(v.x, v.y, h0, l0);
            bfsplit2(v.z, v.w, h1, l1);
            int o = buf * 3072 + slab * 768 + row * 12 + k2s;
            sm[HS_H + o] = h0;  sm[HS_H + o + 1] = h1;
            sm[HS_L + o] = l0;  sm[HS_L + o + 1] = l1;
        }
        // W: 48 cols x 32 k2, pre-packed (uint4 copies)
        for (int e = tid; e < 384; e += 256) {
            int col = e >> 3, q = e & 7;
            int slab = q >> 1, k2s = (q & 1) * 4;
            int o = buf * 2304 + slab * 576 + col * 12 + k2s;
            uint4 vh = *(const uint4*)&whbase[(size_t)col * K2 + kc * 32 + q * 4];
            uint4 vl = *(const uint4*)&wlbase[(size_t)col * K2 + kc * 32 + q * 4];
            *(uint4*)&sm[WS_H + o] = vh;
            *(uint4*)&sm[WS_L + o] = vl;
        }
    };

    for (int t = 0; t < T; t++) {
        const int te = d ? (T - 1 - t) : t;
        const int cd = cnt[te];
        const bool active = (r0 < cd);

        float acc[3][4];
#pragma unroll
        for (int g = 0; g < 3; g++)
#pragma unroll
            for (int c = 0; c < 4; c++) acc[g][c] = 0.f;

        if (active) {
            stage(0, 0, hcur);
            __syncthreads();
            for (int kc = 0; kc < KCH; kc++) {
                const int buf = kc & 1;
                if (kc + 1 < KCH) stage(buf ^ 1, kc + 1, hcur);
#pragma unroll
                for (int slab = 0; slab < 4; slab++) {
                    uint32_t bh[3][2], bl[3][2], r4[4];
                    uint32_t wa = sbase + (WS_H + buf * 2304 + slab * 576
                                           + (wc * 24 + wrow) * 12 + wk2) * 4;
                    ldsm_x4(r4, wa);
                    bh[0][0] = r4[0]; bh[0][1] = r4[1];
                    bh[1][0] = r4[2]; bh[1][1] = r4[3];
                    ldsm_x4(r4, wa + (WS_L - WS_H) * 4);
                    bl[0][0] = r4[0]; bl[0][1] = r4[1];
                    bl[1][0] = r4[2]; bl[1][1] = r4[3];
                    uint32_t wa2 = sbase + (WS_H + buf * 2304 + slab * 576
                                            + (wc * 24 + 16 + x2row) * 12 + x2k2) * 4;
                    uint32_t r2[2];
                    ldsm_x2(r2, wa2);
                    bh[2][0] = r2[0]; bh[2][1] = r2[1];
                    ldsm_x2(r2, wa2 + (WS_L - WS_H) * 4);
                    bl[2][0] = r2[0]; bl[2][1] = r2[1];

                    uint32_t ah[4], al[4];
                    uint32_t aa = sbase + (HS_H + buf * 3072 + slab * 768
                                           + (wr * 16 + arow) * 12 + ak2) * 4;
                    ldsm_x4(ah, aa);
                    ldsm_x4(al, aa + (HS_L - HS_H) * 4);
#pragma unroll
                    for (int g = 0; g < 3; g++) {
                        mma_bf16(acc[g], ah, bh[g]);
                        mma_bf16(acc[g], al, bh[g]);
                        mma_bf16(acc[g], ah, bl[g]);
                    }
                }
                __syncthreads();
            }
        }

        // gate math / copy (each thread owns 4 (row,j) elements w/ all 3 gates)
#pragma unroll
        for (int c = 0; c < 4; c++) {
            int row = r0 + wr * 16 + gid + ((c >> 1) << 3);
            int jj  = jcol0 + wc * 8 + tig * 2 + (c & 1);
            size_t hidx = ((size_t)d * B + row) * H + jj;
            float hold = __ldcg(&hcur[hidx]);
            if (row < cd) {
                int bo = perm[row];
                float hpr = acc[0][c] + b_hh[d * G3 + jj];
                float hpz = acc[1][c] + b_hh[d * G3 + H + jj];
                float hpn = acc[2][c] + b_hh[d * G3 + 2 * H + jj];
                const float* xr = xp + ((size_t)bo * T + te) * (2 * G3) + (size_t)d * G3;
                float rg = fast_sigmoid(xr[jj] + hpr);
                float zg = fast_sigmoid(xr[H + jj] + hpz);
                float ng = fast_tanh(xr[2 * H + jj] + rg * hpn);
                float hnew = (1.f - zg) * ng + zg * hold;
                hnxt[hidx] = hnew;
                out[((size_t)bo * T + te) * (2 * H) + d * H + jj] = hnew;
            } else {
                hnxt[hidx] = hold;
            }
        }

        grid_sync_fast(slots, release, NCTA, &gen);
        float* tmp = hcur; hcur = hnxt; hnxt = tmp;
    }
}

// ---------------- segment means ----------------
__global__ __launch_bounds__(256) void seg_mean_kernel(
    const float* __restrict__ vf, const float* __restrict__ loc,
    const int* __restrict__ v_len,
    float* __restrict__ lmean, float* __restrict__ rmean, float* __restrict__ cat)
{
    const int b = blockIdx.x;
    const int col = blockIdx.y * 256 + threadIdx.x;
    const int vl = v_len[b];
    const float scale = (float)(vl - 1);
    const float l0 = loc[b * 2], l1 = loc[b * 2 + 1];
    const int cond = (l0 <= l1);
    const float lhi = cond ? l0 : 0.f;
    const float rlo = cond ? l1 : 1.f;
    const int lend   = (int)floorf(lhi * scale);
    const int rstart = (int)floorf(rlo * scale);
    const int rend   = vl - 1;
    const int ok_l = (0 <= lend);
    const int ok_r = (rstart <= rend);

    float ls = 0.f, rs = 0.f, gs = 0.f;
    for (int t = 0; t < vl; t++) {
        float v = vf[((size_t)b * TV + t) * 1024 + col];
        gs += v;
        if (ok_l && t <= lend) ls += v;
        if (ok_r && t >= rstart) rs += v;
    }
    float lcnt = ok_l ? (float)(lend + 1) : 1.f;
    float rcnt = ok_r ? (float)(rend - rstart + 1) : 1.f;
    if (lcnt < 1.f) lcnt = 1.f;
    if (rcnt < 1.f) rcnt = 1.f;
    lmean[b * 1024 + col] = ls / lcnt;
    rmean[b * 1024 + col] = rs / rcnt;
    cat[(size_t)b * NCAT + 512 + col] = gs / (float)vl;
}

// ---------------- gather sen_fea ----------------
__global__ void gather_senfea(const float* __restrict__ words,
                              const int* __restrict__ lens,
                              float* __restrict__ out_sf, float* __restrict__ cat)
{
    const int b = blockIdx.x;
    const int t = lens[b] - 1;
    for (int c = threadIdx.x; c < 2 * SHID; c += blockDim.x) {
        float v = words[((size_t)b * TS + t) * (2 * SHID) + c];
        out_sf[(size_t)b * (2 * SHID) + c] = v;
        cat[(size_t)b * NCAT + c] = v;
    }
}

// ---------------- small GEMM with epilogue ----------------
__global__ __launch_bounds__(256) void gemm_small(
    const float* __restrict__ A, const float* __restrict__ W,
    const float* __restrict__ bias, const float* __restrict__ mul, int mulLd,
    float* __restrict__ C, int ldC, int M, int N, int K, int relu)
{
    const int n0 = blockIdx.x * 32, m0 = blockIdx.y * 32;
    __shared__ __align__(16) float As[32][34];
    __shared__ __align__(16) float Wsm[32][34];
    const int tid = threadIdx.x, ty = tid / 16, tx = tid % 16;
    float acc[2][2] = {{0.f, 0.f}, {0.f, 0.f}};

    for (int k0 = 0; k0 < K; k0 += 32) {
        for (int e = tid; e < 1024; e += 256) {
            int r = e / 32, k = e % 32;
            int kg = k0 + k;
            As[k][r]  = (kg < K) ? A[(size_t)(m0 + r) * K + kg] : 0.f;
            Wsm[k][r] = (kg < K) ? W[(size_t)(n0 + r) * K + kg] : 0.f;
        }
        __syncthreads();
#pragma unroll
        for (int k = 0; k < 32; k++) {
            float2 av = *(const float2*)&As[k][ty * 2];
            float2 wv = *(const float2*)&Wsm[k][tx * 2];
            acc[0][0] += av.x * wv.x;  acc[0][1] += av.x * wv.y;
            acc[1][0] += av.y * wv.x;  acc[1][1] += av.y * wv.y;
        }
        __syncthreads();
    }
#pragma unroll
    for (int i = 0; i < 2; i++) {
        int m = m0 + ty * 2 + i;
#pragma unroll
        for (int j = 0; j < 2; j++) {
            int n = n0 + tx * 2 + j;
            float v = acc[i][j] + bias[n];
            if (mul) v *= mul[(size_t)m * mulLd + n];
            if (relu) v = fmaxf(v, 0.f);
            C[(size_t)m * ldC + n] = v;
        }
    }
}

// ---------------- launch ----------------
extern "C" void kernel_launch(void* const* d_in, const int* in_sizes, int n_in,
                              void* d_out, int out_size)
{
    const float* gv     = (const float*)d_in[1];
    const float* sen    = (const float*)d_in[2];
    const float* loc    = (const float*)d_in[5];
    const int*   lens   = (const int*)  d_in[6];
    const int*   v_len  = (const int*)  d_in[7];
    const float* v_w_ih = (const float*)d_in[8];
    const float* v_w_hh = (const float*)d_in[9];
    const float* v_b_ih = (const float*)d_in[10];
    const float* v_b_hh = (const float*)d_in[11];
    const float* s_w_ih = (const float*)d_in[12];
    const float* s_w_hh = (const float*)d_in[13];
    const float* s_b_ih = (const float*)d_in[14];
    const float* s_b_hh = (const float*)d_in[15];
    const float* fc1_w  = (const float*)d_in[16];
    const float* fc1_b  = (const float*)d_in[17];
    const float* fc2_w  = (const float*)d_in[18];
    const float* fc2_b  = (const float*)d_in[19];
    const float* fc3_w  = (const float*)d_in[20];
    const float* fc3_b  = (const float*)d_in[21];
    const float* fc4_w  = (const float*)d_in[22];
    const float* fc4_b  = (const float*)d_in[23];

    float* out    = (float*)d_out;
    float* out_vf = out;
    float* out_sf = out + VF_ELEMS;
    float* out_ft = out + VF_ELEMS + SF_ELEMS;

    float *xp_v, *xp_s, *h_v, *h_s, *words;
    float *lmean, *rmean, *cat, *sproj;
    uint32_t *whv, *wlv, *whs, *wls;
    int *perm_v, *lenp_v, *perm_s, *lenp_s, *cnt_v, *cnt_s;
    unsigned *slots_v, *slots_s, *rel;
    cudaGetSymbolAddress((void**)&xp_v,    g_xp_v);
    cudaGetSymbolAddress((void**)&xp_s,    g_xp_s);
    cudaGetSymbolAddress((void**)&h_v,     g_h_v);
    cudaGetSymbolAddress((void**)&h_s,     g_h_s);
    cudaGetSymbolAddress((void**)&whv,     g_wpkhi_v);
    cudaGetSymbolAddress((void**)&wlv,     g_wpklo_v);
    cudaGetSymbolAddress((void**)&whs,     g_wpkhi_s);
    cudaGetSymbolAddress((void**)&wls,     g_wpklo_s);
    cudaGetSymbolAddress((void**)&words,   g_words);
    cudaGetSymbolAddress((void**)&lmean,   g_lmean);
    cudaGetSymbolAddress((void**)&rmean,   g_rmean);
    cudaGetSymbolAddress((void**)&cat,     g_cat);
    cudaGetSymbolAddress((void**)&sproj,   g_sproj);
    cudaGetSymbolAddress((void**)&perm_v,  g_perm_v);
    cudaGetSymbolAddress((void**)&lenp_v,  g_lenp_v);
    cudaGetSymbolAddress((void**)&perm_s,  g_perm_s);
    cudaGetSymbolAddress((void**)&lenp_s,  g_lenp_s);
    cudaGetSymbolAddress((void**)&cnt_v,   g_cnt_v);
    cudaGetSymbolAddress((void**)&cnt_s,   g_cnt_s);
    cudaGetSymbolAddress((void**)&slots_v, g_slots_v);
    cudaGetSymbolAddress((void**)&slots_s, g_slots_s);
    cudaGetSymbolAddress((void**)&rel,     g_release);

    cudaFuncSetAttribute(gru_v2<512, 256, 32, 128>,
                         cudaFuncAttributeMaxDynamicSharedMemorySize, GRU2_SMEM);
    cudaFuncSetAttribute(gru_v2<256, 40, 16, 64>,
                         cudaFuncAttributeMaxDynamicSharedMemorySize, GRU2_SMEM);
    cudaFuncSetAttribute(gemm_bf16x3,
                         cudaFuncAttributeMaxDynamicSharedMemorySize, GEMM_SMEM);

    // 1. init: sort + counts + barrier state + zero h + zero visual output
    sort_init_kernel<<<1, 128>>>(v_len, lens, perm_v, lenp_v, perm_s, lenp_s,
                                 cnt_v, cnt_s, slots_v, slots_s, rel);
    zero_h_kernel<<<(2*2*B*VHID + 255) / 256, 256>>>(h_v, h_s);
    zero_out_kernel<<<(int)(VF_ELEMS/4 + 255) / 256, 256>>>((float4*)out_vf,
                                                            (int)(VF_ELEMS/4));
    // 2. pre-pack recurrent weights (bf16 hi/lo, gate-interleaved)
    prep_wpk<<<(2*1536*256 + 255) / 256, 256>>>(v_w_hh, whv, wlv, VHID);
    prep_wpk<<<(2*768*128 + 255) / 256, 256>>>(s_w_hh, whs, wls, SHID);

    // 3. input projections (3xBF16, ldmatrix fragments)
    gemm_bf16x3<<<dim3(3072/128, (B*TV)/128), 256, GEMM_SMEM>>>(
        gv,  v_w_ih, v_b_ih, xp_v, B*TV, 3072, VIN, v_len, TV);
    gemm_bf16x3<<<dim3(1536/128, (B*TS)/128), 256, GEMM_SMEM>>>(
        sen, s_w_ih, s_b_ih, xp_s, B*TS, 1536, SIN, lens, TS);

    // 4. persistent visual GRU v2 (128 CTAs, 1 barrier/step)
    gru_v2<512, 256, 32, 128><<<128, 256, GRU2_SMEM>>>(
        xp_v, whv, wlv, v_b_hh, h_v, out_vf, perm_v, cnt_v, slots_v, rel);

    // 5. persistent sentence GRU v2 (64 CTAs)
    gru_v2<256, 40, 16, 64><<<64, 256, GRU2_SMEM>>>(
        xp_s, whs, wls, s_b_hh, h_s, words, perm_s, cnt_s, slots_s, rel + 1);

    // 6. sen_fea gather
    gather_senfea<<<B, 256>>>(words, lens, out_sf, cat);

    // 7. segment means + global mean
    seg_mean_kernel<<<dim3(B, 4), 256>>>(out_vf, loc, v_len, lmean, rmean, cat);

    // 8. FC stack
    gemm_small<<<dim3(LCROSS/32, B/32), 256>>>(out_sf, fc2_w, fc2_b, nullptr, 0,
                                               sproj, LCROSS, B, LCROSS, 2*SHID, 0);
    gemm_small<<<dim3(LCROSS/32, B/32), 256>>>(lmean, fc1_w, fc1_b, sproj, LCROSS,
                                               cat + 1536, NCAT, B, LCROSS, 2*VHID, 1);
    gemm_small<<<dim3(LCROSS/32, B/32), 256>>>(rmean, fc1_w, fc1_b, sproj, LCROSS,
                                               cat + 2048, NCAT, B, LCROSS, 2*VHID, 1);
    gemm_small<<<dim3(NLOC/32, B/32), 256>>>(loc, fc3_w, fc3_b, nullptr, 0,
                                             cat + 2560, NCAT, B, NLOC, 2, 1);
    gemm_small<<<dim3(NFEAT/32, B/32), 256>>>(cat, fc4_w, fc4_b, nullptr, 0,
                                              out_ft, NFEAT, B, NFEAT, NCAT, 1);
}

// round 11
// speedup vs baseline: 1.3347x; 1.3347x over previous
#include <cuda_runtime.h>
#include <cuda_bf16.h>
#include <math.h>
#include <stdint.h>

// ---------------- problem constants ----------------
#define B        128
#define TV       256
#define TS       40
#define VIN      1024
#define VHID     512
#define SIN      300
#define SHID     256
#define NCAT     2624
#define NFEAT    1024
#define LCROSS   512
#define NLOC     64

#define VF_ELEMS   ((size_t)B*TV*2*VHID)
#define SF_ELEMS   ((size_t)B*2*SHID)

// ---------------- scratch (__device__ globals) ----------------
__device__ float g_xp_v[(size_t)B*TV*3072];
__device__ float g_xp_s[(size_t)B*TS*1536];
__device__ float g_h_v[2*B*VHID];               // single buffer, in-place
__device__ float g_h_s[2*B*SHID];
__device__ float g_part_v[8*2*B*1536];
__device__ float g_part_s[4*2*B*768];
__device__ float g_words[(size_t)B*TS*2*SHID];
__device__ float g_lmean[B*1024];
__device__ float g_rmean[B*1024];
__device__ float g_cat[B*NCAT];
__device__ float g_sproj[B*LCROSS];
__device__ int   g_perm_v[B], g_lenp_v[B];
__device__ int   g_perm_s[B], g_lenp_s[B];
__device__ int   g_cnt_v[TV], g_cnt_s[TS];      // cnt[t] = #rows with len > t
__device__ unsigned g_bar[4];

// ---------------- init ----------------
__global__ void sort_init_kernel(const int* __restrict__ v_len,
                                 const int* __restrict__ lens,
                                 int* pv, int* lv, int* ps, int* ls,
                                 int* cv, int* cs, unsigned* bar)
{
    int i = threadIdx.x;
    if (i < 4) bar[i] = 0u;
    int a = v_len[i], rank = 0;
    for (int j = 0; j < B; j++) {
        int c = v_len[j];
        rank += (c > a) || (c == a && j < i);
    }
    pv[rank] = i; lv[rank] = a;
    a = lens[i]; rank = 0;
    for (int j = 0; j < B; j++) {
        int c = lens[j];
        rank += (c > a) || (c == a && j < i);
    }
    ps[rank] = i; ls[rank] = a;

    for (int t = i; t < TV; t += 128) {
        int c = 0;
        for (int j = 0; j < B; j++) c += (v_len[j] > t);
        cv[t] = c;
    }
    for (int t = i; t < TS; t += 128) {
        int c = 0;
        for (int j = 0; j < B; j++) c += (lens[j] > t);
        cs[t] = c;
    }
}

__global__ void zero_h_kernel(float* hv, float* hs) {
    int i = blockIdx.x * blockDim.x + threadIdx.x;
    if (i < 2*B*VHID) hv[i] = 0.f;
    if (i < 2*B*SHID) hs[i] = 0.f;
}

__global__ void zero_out_kernel(float4* p, int n4) {
    int i = blockIdx.x * blockDim.x + threadIdx.x;
    if (i < n4) p[i] = make_float4(0.f, 0.f, 0.f, 0.f);
}

// ---------------- numeric helpers ----------------
__device__ __forceinline__ uint32_t tf32_rna(float x) {
    uint32_t r;
    asm("cvt.rna.tf32.f32 %0, %1;" : "=r"(r) : "f"(x));
    return r;
}
__device__ __forceinline__ void mma_tf32(float* d, const uint32_t* a, const uint32_t* b) {
    asm volatile(
        "mma.sync.aligned.m16n8k8.row.col.f32.tf32.tf32.f32 "
        "{%0,%1,%2,%3}, {%4,%5,%6,%7}, {%8,%9}, {%0,%1,%2,%3};"
        : "+f"(d[0]), "+f"(d[1]), "+f"(d[2]), "+f"(d[3])
        : "r"(a[0]), "r"(a[1]), "r"(a[2]), "r"(a[3]), "r"(b[0]), "r"(b[1]));
}
__device__ __forceinline__ void mma_bf16(float* d, const uint32_t* a, const uint32_t* b) {
    asm volatile(
        "mma.sync.aligned.m16n8k16.row.col.f32.bf16.bf16.f32 "
        "{%0,%1,%2,%3}, {%4,%5,%6,%7}, {%8,%9}, {%0,%1,%2,%3};"
        : "+f"(d[0]), "+f"(d[1]), "+f"(d[2]), "+f"(d[3])
        : "r"(a[0]), "r"(a[1]), "r"(a[2]), "r"(a[3]), "r"(b[0]), "r"(b[1]));
}
__device__ __forceinline__ void ldsm_x4(uint32_t* r, uint32_t saddr) {
    asm volatile("ldmatrix.sync.aligned.m8n8.x4.shared.b16 {%0,%1,%2,%3}, [%4];"
                 : "=r"(r[0]), "=r"(r[1]), "=r"(r[2]), "=r"(r[3]) : "r"(saddr));
}
__device__ __forceinline__ uint32_t bfpack(__nv_bfloat16 lo, __nv_bfloat16 hi) {
    uint32_t l = __bfloat16_as_ushort(lo);
    uint32_t h = __bfloat16_as_ushort(hi);
    return l | (h << 16);
}
__device__ __forceinline__ void bfsplit2(float x0, float x1,
                                         uint32_t& hi, uint32_t& lo) {
    __nv_bfloat16 h0 = __float2bfloat16_rn(x0);
    __nv_bfloat16 h1 = __float2bfloat16_rn(x1);
    hi = bfpack(h0, h1);
    __nv_bfloat16 l0 = __float2bfloat16_rn(x0 - __bfloat162float(h0));
    __nv_bfloat16 l1 = __float2bfloat16_rn(x1 - __bfloat162float(h1));
    lo = bfpack(l0, l1);
}
__device__ __forceinline__ float4 ld_guard4(const float* p, int kg, int K) {
    if (kg + 4 <= K) return *(const float4*)p;
    float4 v;
    v.x = (kg     < K) ? p[0] : 0.f;
    v.y = (kg + 1 < K) ? p[1] : 0.f;
    v.z = (kg + 2 < K) ? p[2] : 0.f;
    v.w = (kg + 3 < K) ? p[3] : 0.f;
    return v;
}
__device__ __forceinline__ float fast_sigmoid(float x) {
    return __fdividef(1.f, 1.f + __expf(-x));
}
__device__ __forceinline__ float fast_tanh(float x) {
    return __fdividef(2.f, 1.f + __expf(-2.f * x)) - 1.f;
}

// ---------------- 3xBF16 tensor-core GEMM with ldmatrix fragments ----------
#define GEMM_SMEM (4 * 2 * 128 * 12 * 4)     // 49152 B
__global__ __launch_bounds__(256, 2) void gemm_bf16x3(
    const float* __restrict__ A, const float* __restrict__ W,
    const float* __restrict__ bias, float* __restrict__ C,
    int M, int N, int K, const int* __restrict__ lens, int T)
{
    extern __shared__ uint32_t dsm[];
    const int AH = 0, AL = 2*128*12, WH = 2*AL, WL = 3*AL;
    __shared__ int s_any;

    const int n0 = blockIdx.x * 128;
    const int m0 = blockIdx.y * 128;
    const int tid = threadIdx.x;

    if (lens) {
        if (tid == 0) {
            int any = 0;
            for (int r = 0; r < 128; r++) {
                int row = m0 + r;
                if (row % T < lens[row / T]) { any = 1; break; }
            }
            s_any = any;
        }
        __syncthreads();
        if (!s_any) return;
    }

    const int wid  = tid / 32, lane = tid % 32;
    const int wm   = (wid / 4) * 64;
    const int wn   = (wid % 4) * 32;
    const int gid  = lane >> 2, tig = lane & 3;
    const int quad = lane >> 3, lrow = lane & 7;
    const int arow = ((quad & 1) << 3) + lrow;
    const int ak2  = (quad >> 1) * 4;
    const int wrow = ((quad >> 1) << 3) + lrow;
    const int wk2  = (quad & 1) * 4;
    const uint32_t sbase = (uint32_t)__cvta_generic_to_shared(dsm);
    const int niter = (K + 15) >> 4;

    const int c0r = tid >> 2,          c0k = (tid & 3) * 4;
    const int c1r = (tid + 256) >> 2,  c1k = ((tid + 256) & 3) * 4;

    float acc[4][4][4];
#pragma unroll
    for (int i = 0; i < 4; i++)
#pragma unroll
        for (int j = 0; j < 4; j++)
#pragma unroll
            for (int c = 0; c < 4; c++) acc[i][j][c] = 0.f;

    float4 ra0, ra1, rw0, rw1;
    ra0 = ld_guard4(A + (size_t)(m0 + c0r) * K + c0k, c0k, K);
    ra1 = ld_guard4(A + (size_t)(m0 + c1r) * K + c1k, c1k, K);
    rw0 = ld_guard4(W + (size_t)(n0 + c0r) * K + c0k, c0k, K);
    rw1 = ld_guard4(W + (size_t)(n0 + c1r) * K + c1k, c1k, K);

    for (int kt = 0; kt < niter; kt++) {
        const int buf = kt & 1;
        const int bo = buf * 128;
        {
            uint32_t h, l;
            int k2 = c0k >> 1;
            int r0i = (bo + c0r) * 12, r1i = (bo + c1r) * 12;
            bfsplit2(ra0.x, ra0.y, h, l); dsm[AH + r0i + k2] = h;     dsm[AL + r0i + k2] = l;
            bfsplit2(ra0.z, ra0.w, h, l); dsm[AH + r0i + k2 + 1] = h; dsm[AL + r0i + k2 + 1] = l;
            bfsplit2(rw0.x, rw0.y, h, l); dsm[WH + r0i + k2] = h;     dsm[WL + r0i + k2] = l;
            bfsplit2(rw0.z, rw0.w, h, l); dsm[WH + r0i + k2 + 1] = h; dsm[WL + r0i + k2 + 1] = l;
            k2 = c1k >> 1;
            bfsplit2(ra1.x, ra1.y, h, l); dsm[AH + r1i + k2] = h;     dsm[AL + r1i + k2] = l;
            bfsplit2(ra1.z, ra1.w, h, l); dsm[AH + r1i + k2 + 1] = h; dsm[AL + r1i + k2 + 1] = l;
            bfsplit2(rw1.x, rw1.y, h, l); dsm[WH + r1i + k2] = h;     dsm[WL + r1i + k2] = l;
            bfsplit2(rw1.z, rw1.w, h, l); dsm[WH + r1i + k2 + 1] = h; dsm[WL + r1i + k2 + 1] = l;
        }
        __syncthreads();

        if (kt + 1 < niter) {
            const int kg = (kt + 1) * 16;
            ra0 = ld_guard4(A + (size_t)(m0 + c0r) * K + kg + c0k, kg + c0k, K);
            ra1 = ld_guard4(A + (size_t)(m0 + c1r) * K + kg + c1k, kg + c1k, K);
            rw0 = ld_guard4(W + (size_t)(n0 + c0r) * K + kg + c0k, kg + c0k, K);
            rw1 = ld_guard4(W + (size_t)(n0 + c1r) * K + kg + c1k, kg + c1k, K);
        }

        uint32_t bh[4][2], bl[4][2];
#pragma unroll
        for (int jp = 0; jp < 2; jp++) {
            uint32_t r[4];
            uint32_t a = sbase + (WH + (bo + wn + jp * 16 + wrow) * 12 + wk2) * 4;
            ldsm_x4(r, a);
            bh[jp*2][0] = r[0]; bh[jp*2][1] = r[1];
            bh[jp*2+1][0] = r[2]; bh[jp*2+1][1] = r[3];
            ldsm_x4(r, a + (WL - WH) * 4);
            bl[jp*2][0] = r[0]; bl[jp*2][1] = r[1];
            bl[jp*2+1][0] = r[2]; bl[jp*2+1][1] = r[3];
        }
#pragma unroll
        for (int mi = 0; mi < 4; mi++) {
            uint32_t ah[4], al[4];
            uint32_t a = sbase + (AH + (bo + wm + mi * 16 + arow) * 12 + ak2) * 4;
            ldsm_x4(ah, a);
            ldsm_x4(al, a + (AL - AH) * 4);
#pragma unroll
            for (int j = 0; j < 4; j++) {
                mma_bf16(acc[mi][j], ah, bh[j]);
                mma_bf16(acc[mi][j], al, bh[j]);
                mma_bf16(acc[mi][j], ah, bl[j]);
            }
        }
    }

#pragma unroll
    for (int i = 0; i < 4; i++) {
#pragma unroll
        for (int j = 0; j < 4; j++) {
            int col = n0 + wn + j * 8 + tig * 2;
            float b0 = bias[col], b1 = bias[col + 1];
            int r0g = m0 + wm + i * 16 + gid;
            *(float2*)&C[(size_t)r0g * N + col] =
                make_float2(acc[i][j][0] + b0, acc[i][j][1] + b1);
            *(float2*)&C[(size_t)(r0g + 8) * N + col] =
                make_float2(acc[i][j][2] + b0, acc[i][j][3] + b1);
        }
    }
}

// ---------------- software grid barrier (R8 atomic version) ----------------
__device__ __forceinline__ void grid_sync(unsigned* bar, int ncta, unsigned* gen)
{
    __syncthreads();
    if (threadIdx.x == 0) {
        unsigned target = *gen + 1u;
        __threadfence();
        unsigned arr = atomicAdd(&bar[0], 1u);
        if (arr == (unsigned)(ncta - 1)) {
            atomicExch(&bar[0], 0u);
            __threadfence();
            atomicExch(&bar[1], target);
        } else {
            while (*(volatile unsigned*)&bar[1] < target) { }
        }
        __threadfence();
        *gen = target;
    }
    __syncthreads();
}

// ---------------- persistent GRU: tensor phase1, valid-only phase2 ---------
// h updated IN PLACE (barriers order phase1 reads vs phase2 writes).
// out pre-zeroed; phase2 touches only valid (dir,row) prefix, 2 j per thread.
template<int H, int G3, int T, int NCT, int KS>
__global__ __launch_bounds__(256, 2) void gru_persistent(
    const float* __restrict__ xp, const float* __restrict__ w_hh,
    const float* __restrict__ b_hh, float* __restrict__ hbuf,
    float* __restrict__ part, float* __restrict__ out,
    const int* __restrict__ perm, const int* __restrict__ cnt,
    unsigned* __restrict__ bar)
{
    constexpr int KC = 64;
    constexpr int NCTA = 2 * NCT * KS;
    constexpr int H2 = H / 2;
    extern __shared__ float sm[];
    uint32_t* Wh = (uint32_t*)sm;             // [KC][98]
    uint32_t* Wl = Wh + KC * 98;
    float*    Hs = (float*)(Wl + KC * 98);    // [KC][132]

    const int cta = blockIdx.x;
    const int d   = cta / (NCT * KS);
    const int ct  = (cta % (NCT * KS)) / KS;
    const int ks  = cta % KS;
    const int c0  = ct * 96;
    const int k0  = ks * KC;
    const int tid = threadIdx.x;
    const int wid = tid / 32, lane = tid % 32;
    const int gid = lane >> 2, tig = lane & 3;
    const int wm  = (wid >> 1) * 32;
    const int wn  = (wid & 1) * 48;

    for (int e = tid; e < KC * 96; e += 256) {
        int k = e % KC, c = e / KC;
        float w = w_hh[((size_t)d * G3 + c0 + c) * H + k0 + k];
        uint32_t wh = tf32_rna(w);
        Wh[k * 98 + c] = wh;
        Wl[k * 98 + c] = tf32_rna(w - __uint_as_float(wh));
    }

    unsigned gen = 0;
    const int nth = NCTA * 256;

    for (int t = 0; t < T; t++) {
        const int cnt0 = cnt[t];
        const int cnt1 = cnt[T - 1 - t];
        const int cd   = (d == 0) ? cnt0 : cnt1;
        const int rc   = (cd + 31) & ~31;

        for (int e = tid; e < KC * rc; e += 256) {
            int k = e % KC, r = e / KC;
            Hs[k * 132 + r] = hbuf[((size_t)d * B + r) * H + k0 + k];
        }
        __syncthreads();

        if (wm < cd) {
            float acc[2][6][4];
#pragma unroll
            for (int i = 0; i < 2; i++)
#pragma unroll
                for (int j = 0; j < 6; j++)
#pragma unroll
                    for (int c = 0; c < 4; c++) acc[i][j][c] = 0.f;

#pragma unroll
            for (int k8 = 0; k8 < KC / 8; k8++) {
                const int kb = k8 * 8;
                uint32_t bh[6][2], bl[6][2];
#pragma unroll
                for (int j = 0; j < 6; j++) {
                    int c = wn + j * 8 + gid;
                    bh[j][0] = Wh[(kb + tig) * 98 + c];
                    bh[j][1] = Wh[(kb + tig + 4) * 98 + c];
                    bl[j][0] = Wl[(kb + tig) * 98 + c];
                    bl[j][1] = Wl[(kb + tig + 4) * 98 + c];
                }
#pragma unroll
                for (int mi = 0; mi < 2; mi++) {
                    int r = wm + mi * 16 + gid;
                    float h0 = Hs[(kb + tig) * 132 + r];
                    float h1 = Hs[(kb + tig) * 132 + r + 8];
                    float h2 = Hs[(kb + tig + 4) * 132 + r];
                    float h3 = Hs[(kb + tig + 4) * 132 + r + 8];
                    uint32_t ah[4], al[4];
                    ah[0] = tf32_rna(h0); al[0] = tf32_rna(h0 - __uint_as_float(ah[0]));
                    ah[1] = tf32_rna(h1); al[1] = tf32_rna(h1 - __uint_as_float(ah[1]));
                    ah[2] = tf32_rna(h2); al[2] = tf32_rna(h2 - __uint_as_float(ah[2]));
                    ah[3] = tf32_rna(h3); al[3] = tf32_rna(h3 - __uint_as_float(ah[3]));
#pragma unroll
                    for (int j = 0; j < 6; j++) {
                        mma_tf32(acc[mi][j], ah, bh[j]);
                        mma_tf32(acc[mi][j], al, bh[j]);
                        mma_tf32(acc[mi][j], ah, bl[j]);
                    }
                }
            }
#pragma unroll
            for (int mi = 0; mi < 2; mi++) {
                int r = wm + mi * 16 + gid;
#pragma unroll
                for (int j = 0; j < 6; j++) {
                    int col = c0 + wn + j * 8 + tig * 2;
                    float* p0 = part + (((size_t)ks * 2 + d) * B + r) * G3 + col;
                    float* p1 = part + (((size_t)ks * 2 + d) * B + r + 8) * G3 + col;
                    *(float2*)p0 = make_float2(acc[mi][j][0], acc[mi][j][1]);
                    *(float2*)p1 = make_float2(acc[mi][j][2], acc[mi][j][3]);
                }
            }
        }
        grid_sync(bar, NCTA, &gen);

        // phase2: valid elements only, 2 consecutive j per thread (float2 IO)
        const int n0e = cnt0 * H2;
        const int total = n0e + cnt1 * H2;
        for (int it = cta * 256 + tid; it < total; it += nth) {
            int dd = (it >= n0e);
            int loc = dd ? (it - n0e) : it;
            int rr = loc / H2, j = (loc % H2) * 2;
            int te = dd ? (T - 1 - t) : t;
            int bo = perm[rr];
            float2 hold = *(const float2*)&hbuf[((size_t)dd * B + rr) * H + j];
            float2 hpr = make_float2(0.f, 0.f);
            float2 hpz = make_float2(0.f, 0.f);
            float2 hpn = make_float2(0.f, 0.f);
#pragma unroll
            for (int s = 0; s < KS; s++) {
                const float* pb = part + (((size_t)s * 2 + dd) * B + rr) * G3;
                float2 v;
                v = *(const float2*)(pb + j);         hpr.x += v.x; hpr.y += v.y;
                v = *(const float2*)(pb + H + j);     hpz.x += v.x; hpz.y += v.y;
                v = *(const float2*)(pb + 2 * H + j); hpn.x += v.x; hpn.y += v.y;
            }
            const float* bb = b_hh + (size_t)dd * G3;
            float2 br = *(const float2*)(bb + j);
            float2 bz = *(const float2*)(bb + H + j);
            float2 bn = *(const float2*)(bb + 2 * H + j);
            const float* xr = xp + ((size_t)bo * T + te) * (2 * G3) + (size_t)dd * G3;
            float2 xrv = *(const float2*)(xr + j);
            float2 xzv = *(const float2*)(xr + H + j);
            float2 xnv = *(const float2*)(xr + 2 * H + j);
            float rg0 = fast_sigmoid(xrv.x + hpr.x + br.x);
            float rg1 = fast_sigmoid(xrv.y + hpr.y + br.y);
            float zg0 = fast_sigmoid(xzv.x + hpz.x + bz.x);
            float zg1 = fast_sigmoid(xzv.y + hpz.y + bz.y);
            float ng0 = fast_tanh(xnv.x + rg0 * (hpn.x + bn.x));
            float ng1 = fast_tanh(xnv.y + rg1 * (hpn.y + bn.y));
            float2 hnew = make_float2((1.f - zg0) * ng0 + zg0 * hold.x,
                                      (1.f - zg1) * ng1 + zg1 * hold.y);
            *(float2*)&hbuf[((size_t)dd * B + rr) * H + j] = hnew;
            *(float2*)&out[((size_t)bo * T + te) * (2 * H) + dd * H + j] = hnew;
        }
        grid_sync(bar, NCTA, &gen);
    }
}

// ---------------- segment means ----------------
__global__ __launch_bounds__(256) void seg_mean_kernel(
    const float* __restrict__ vf, const float* __restrict__ loc,
    const int* __restrict__ v_len,
    float* __restrict__ lmean, float* __restrict__ rmean, float* __restrict__ cat)
{
    const int b = blockIdx.x;
    const int col = blockIdx.y * 256 + threadIdx.x;
    const int vl = v_len[b];
    const float scale = (float)(vl - 1);
    const float l0 = loc[b * 2], l1 = loc[b * 2 + 1];
    const int cond = (l0 <= l1);
    const float lhi = cond ? l0 : 0.f;
    const float rlo = cond ? l1 : 1.f;
    const int lend   = (int)floorf(lhi * scale);
    const int rstart = (int)floorf(rlo * scale);
    const int rend   = vl - 1;
    const int ok_l = (0 <= lend);
    const int ok_r = (rstart <= rend);

    float ls = 0.f, rs = 0.f, gs = 0.f;
    for (int t = 0; t < vl; t++) {       // all windows live in [0, vl)
        float v = vf[((size_t)b * TV + t) * 1024 + col];
        gs += v;
        if (ok_l && t <= lend) ls += v;
        if (ok_r && t >= rstart) rs += v;
    }
    float lcnt = ok_l ? (float)(lend + 1) : 1.f;
    float rcnt = ok_r ? (float)(rend - rstart + 1) : 1.f;
    if (lcnt < 1.f) lcnt = 1.f;
    if (rcnt < 1.f) rcnt = 1.f;
    lmean[b * 1024 + col] = ls / lcnt;
    rmean[b * 1024 + col] = rs / rcnt;
    cat[(size_t)b * NCAT + 512 + col] = gs / (float)vl;
}

// ---------------- gather sen_fea ----------------
__global__ void gather_senfea(const float* __restrict__ words,
                              const int* __restrict__ lens,
                              float* __restrict__ out_sf, float* __restrict__ cat)
{
    const int b = blockIdx.x;
    const int t = lens[b] - 1;
    for (int c = threadIdx.x; c < 2 * SHID; c += blockDim.x) {
        float v = words[((size_t)b * TS + t) * (2 * SHID) + c];
        out_sf[(size_t)b * (2 * SHID) + c] = v;
        cat[(size_t)b * NCAT + c] = v;
    }
}

// ---------------- small GEMM with epilogue ----------------
__global__ __launch_bounds__(256) void gemm_small(
    const float* __restrict__ A, const float* __restrict__ W,
    const float* __restrict__ bias, const float* __restrict__ mul, int mulLd,
    float* __restrict__ C, int ldC, int M, int N, int K, int relu)
{
    const int n0 = blockIdx.x * 32, m0 = blockIdx.y * 32;
    __shared__ __align__(16) float As[32][34];
    __shared__ __align__(16) float Wsm[32][34];
    const int tid = threadIdx.x, ty = tid / 16, tx = tid % 16;
    float acc[2][2] = {{0.f, 0.f}, {0.f, 0.f}};

    for (int k0 = 0; k0 < K; k0 += 32) {
        for (int e = tid; e < 1024; e += 256) {
            int r = e / 32, k = e % 32;
            int kg = k0 + k;
            As[k][r]  = (kg < K) ? A[(size_t)(m0 + r) * K + kg] : 0.f;
            Wsm[k][r] = (kg < K) ? W[(size_t)(n0 + r) * K + kg] : 0.f;
        }
        __syncthreads();
#pragma unroll
        for (int k = 0; k < 32; k++) {
            float2 av = *(const float2*)&As[k][ty * 2];
            float2 wv = *(const float2*)&Wsm[k][tx * 2];
            acc[0][0] += av.x * wv.x;  acc[0][1] += av.x * wv.y;
            acc[1][0] += av.y * wv.x;  acc[1][1] += av.y * wv.y;
        }
        __syncthreads();
    }
#pragma unroll
    for (int i = 0; i < 2; i++) {
        int m = m0 + ty * 2 + i;
#pragma unroll
        for (int j = 0; j < 2; j++) {
            int n = n0 + tx * 2 + j;
            float v = acc[i][j] + bias[n];
            if (mul) v *= mul[(size_t)m * mulLd + n];
            if (relu) v = fmaxf(v, 0.f);
            C[(size_t)m * ldC + n] = v;
        }
    }
}

// ---------------- launch ----------------
extern "C" void kernel_launch(void* const* d_in, const int* in_sizes, int n_in,
                              void* d_out, int out_size)
{
    const float* gv     = (const float*)d_in[1];
    const float* sen    = (const float*)d_in[2];
    const float* loc    = (const float*)d_in[5];
    const int*   lens   = (const int*)  d_in[6];
    const int*   v_len  = (const int*)  d_in[7];
    const float* v_w_ih = (const float*)d_in[8];
    const float* v_w_hh = (const float*)d_in[9];
    const float* v_b_ih = (const float*)d_in[10];
    const float* v_b_hh = (const float*)d_in[11];
    const float* s_w_ih = (const float*)d_in[12];
    const float* s_w_hh = (const float*)d_in[13];
    const float* s_b_ih = (const float*)d_in[14];
    const float* s_b_hh = (const float*)d_in[15];
    const float* fc1_w  = (const float*)d_in[16];
    const float* fc1_b  = (const float*)d_in[17];
    const float* fc2_w  = (const float*)d_in[18];
    const float* fc2_b  = (const float*)d_in[19];
    const float* fc3_w  = (const float*)d_in[20];
    const float* fc3_b  = (const float*)d_in[21];
    const float* fc4_w  = (const float*)d_in[22];
    const float* fc4_b  = (const float*)d_in[23];

    float* out    = (float*)d_out;
    float* out_vf = out;
    float* out_sf = out + VF_ELEMS;
    float* out_ft = out + VF_ELEMS + SF_ELEMS;

    float *xp_v, *xp_s, *h_v, *h_s, *part_v, *part_s, *words;
    float *lmean, *rmean, *cat, *sproj;
    int *perm_v, *lenp_v, *perm_s, *lenp_s, *cnt_v, *cnt_s;
    unsigned* bar;
    cudaGetSymbolAddress((void**)&xp_v,   g_xp_v);
    cudaGetSymbolAddress((void**)&xp_s,   g_xp_s);
    cudaGetSymbolAddress((void**)&h_v,    g_h_v);
    cudaGetSymbolAddress((void**)&h_s,    g_h_s);
    cudaGetSymbolAddress((void**)&part_v, g_part_v);
    cudaGetSymbolAddress((void**)&part_s, g_part_s);
    cudaGetSymbolAddress((void**)&words,  g_words);
    cudaGetSymbolAddress((void**)&lmean,  g_lmean);
    cudaGetSymbolAddress((void**)&rmean,  g_rmean);
    cudaGetSymbolAddress((void**)&cat,    g_cat);
    cudaGetSymbolAddress((void**)&sproj,  g_sproj);
    cudaGetSymbolAddress((void**)&perm_v, g_perm_v);
    cudaGetSymbolAddress((void**)&lenp_v, g_lenp_v);
    cudaGetSymbolAddress((void**)&perm_s, g_perm_s);
    cudaGetSymbolAddress((void**)&lenp_s, g_lenp_s);
    cudaGetSymbolAddress((void**)&cnt_v,  g_cnt_v);
    cudaGetSymbolAddress((void**)&cnt_s,  g_cnt_s);
    cudaGetSymbolAddress((void**)&bar,    g_bar);

    const int GRU_SMEM = (2 * 64 * 98 + 64 * 132) * 4;
    cudaFuncSetAttribute(gru_persistent<512, 1536, 256, 16, 8>,
                         cudaFuncAttributeMaxDynamicSharedMemorySize, GRU_SMEM);
    cudaFuncSetAttribute(gru_persistent<256, 768, 40, 8, 4>,
                         cudaFuncAttributeMaxDynamicSharedMemorySize, GRU_SMEM);
    cudaFuncSetAttribute(gemm_bf16x3,
                         cudaFuncAttributeMaxDynamicSharedMemorySize, GEMM_SMEM);

    // 1. sort + counts + zero h + zero visual output region
    sort_init_kernel<<<1, 128>>>(v_len, lens, perm_v, lenp_v, perm_s, lenp_s,
                                 cnt_v, cnt_s, bar);
    zero_h_kernel<<<(2*B*VHID + 255) / 256, 256>>>(h_v, h_s);
    zero_out_kernel<<<(int)(VF_ELEMS/4 + 255) / 256, 256>>>((float4*)out_vf,
                                                            (int)(VF_ELEMS/4));

    // 2. input projections (3xBF16, ldmatrix fragments)
    gemm_bf16x3<<<dim3(3072/128, (B*TV)/128), 256, GEMM_SMEM>>>(
        gv,  v_w_ih, v_b_ih, xp_v, B*TV, 3072, VIN, v_len, TV);
    gemm_bf16x3<<<dim3(1536/128, (B*TS)/128), 256, GEMM_SMEM>>>(
        sen, s_w_ih, s_b_ih, xp_s, B*TS, 1536, SIN, lens, TS);

    // 3. persistent visual GRU
    gru_persistent<512, 1536, 256, 16, 8><<<256, 256, GRU_SMEM>>>(
        xp_v, v_w_hh, v_b_hh, h_v, part_v, out_vf, perm_v, cnt_v, bar);

    // 4. persistent sentence GRU
    gru_persistent<256, 768, 40, 8, 4><<<64, 256, GRU_SMEM>>>(
        xp_s, s_w_hh, s_b_hh, h_s, part_s, words, perm_s, cnt_s, bar + 2);

    // 5. sen_fea gather
    gather_senfea<<<B, 256>>>(words, lens, out_sf, cat);

    // 6. segment means + global mean
    seg_mean_kernel<<<dim3(B, 4), 256>>>(out_vf, loc, v_len, lmean, rmean, cat);

    // 7. FC stack
    gemm_small<<<dim3(LCROSS/32, B/32), 256>>>(out_sf, fc2_w, fc2_b, nullptr, 0,
                                               sproj, LCROSS, B, LCROSS, 2*SHID, 0);
    gemm_small<<<dim3(LCROSS/32, B/32), 256>>>(lmean, fc1_w, fc1_b, sproj, LCROSS,
                                               cat + 1536, NCAT, B, LCROSS, 2*VHID, 1);
    gemm_small<<<dim3(LCROSS/32, B/32), 256>>>(rmean, fc1_w, fc1_b, sproj, LCROSS,
                                               cat + 2048, NCAT, B, LCROSS, 2*VHID, 1);
    gemm_small<<<dim3(NLOC/32, B/32), 256>>>(loc, fc3_w, fc3_b, nullptr, 0,
                                             cat + 2560, NCAT, B, NLOC, 2, 1);
    gemm_small<<<dim3(NFEAT/32, B/32), 256>>>(cat, fc4_w, fc4_b, nullptr, 0,
                                              out_ft, NFEAT, B, NFEAT, NCAT, 1);
}

// round 12
// speedup vs baseline: 1.7442x; 1.3068x over previous
#include <cuda_runtime.h>
#include <cuda_bf16.h>
#include <math.h>
#include <stdint.h>

// ---------------- problem constants ----------------
#define B        128
#define TV       256
#define TS       40
#define VIN      1024
#define VHID     512
#define SIN      300
#define SHID     256
#define NCAT     2624
#define NFEAT    1024
#define LCROSS   512
#define NLOC     64

#define VF_ELEMS   ((size_t)B*TV*2*VHID)
#define SF_ELEMS   ((size_t)B*2*SHID)

// ---------------- scratch (__device__ globals) ----------------
__device__ float g_xp_v[(size_t)B*TV*3072];
__device__ float g_xp_s[(size_t)B*TS*1536];
__device__ float g_h_v[2*B*VHID];               // single buffer, in-place
__device__ float g_h_s[2*B*SHID];
__device__ float g_part_v[8*2*B*1536];
__device__ float g_part_s[4*2*B*768];
__device__ float g_words[(size_t)B*TS*2*SHID];
__device__ float g_lmean[B*1024];
__device__ float g_rmean[B*1024];
__device__ float g_cat[B*NCAT];
__device__ float g_sproj[B*LCROSS];
__device__ int   g_perm_v[B], g_lenp_v[B];
__device__ int   g_perm_s[B], g_lenp_s[B];
__device__ int   g_cnt_v[TV], g_cnt_s[TS];      // cnt[t] = #rows with len > t
__device__ unsigned g_bar[4];

// ---------------- init ----------------
__global__ void sort_init_kernel(const int* __restrict__ v_len,
                                 const int* __restrict__ lens,
                                 int* pv, int* lv, int* ps, int* ls,
                                 int* cv, int* cs, unsigned* bar)
{
    int i = threadIdx.x;
    if (i < 4) bar[i] = 0u;
    int a = v_len[i], rank = 0;
    for (int j = 0; j < B; j++) {
        int c = v_len[j];
        rank += (c > a) || (c == a && j < i);
    }
    pv[rank] = i; lv[rank] = a;
    a = lens[i]; rank = 0;
    for (int j = 0; j < B; j++) {
        int c = lens[j];
        rank += (c > a) || (c == a && j < i);
    }
    ps[rank] = i; ls[rank] = a;

    for (int t = i; t < TV; t += 128) {
        int c = 0;
        for (int j = 0; j < B; j++) c += (v_len[j] > t);
        cv[t] = c;
    }
    for (int t = i; t < TS; t += 128) {
        int c = 0;
        for (int j = 0; j < B; j++) c += (lens[j] > t);
        cs[t] = c;
    }
}

__global__ void zero_h_kernel(float* hv, float* hs) {
    int i = blockIdx.x * blockDim.x + threadIdx.x;
    if (i < 2*B*VHID) hv[i] = 0.f;
    if (i < 2*B*SHID) hs[i] = 0.f;
}

__global__ void zero_out_kernel(float4* p, int n4) {
    int i = blockIdx.x * blockDim.x + threadIdx.x;
    if (i < n4) p[i] = make_float4(0.f, 0.f, 0.f, 0.f);
}

// ---------------- numeric helpers ----------------
__device__ __forceinline__ void mma_bf16(float* d, const uint32_t* a, const uint32_t* b) {
    asm volatile(
        "mma.sync.aligned.m16n8k16.row.col.f32.bf16.bf16.f32 "
        "{%0,%1,%2,%3}, {%4,%5,%6,%7}, {%8,%9}, {%0,%1,%2,%3};"
        : "+f"(d[0]), "+f"(d[1]), "+f"(d[2]), "+f"(d[3])
        : "r"(a[0]), "r"(a[1]), "r"(a[2]), "r"(a[3]), "r"(b[0]), "r"(b[1]));
}
__device__ __forceinline__ void ldsm_x4(uint32_t* r, uint32_t saddr) {
    asm volatile("ldmatrix.sync.aligned.m8n8.x4.shared.b16 {%0,%1,%2,%3}, [%4];"
                 : "=r"(r[0]), "=r"(r[1]), "=r"(r[2]), "=r"(r[3]) : "r"(saddr));
}
__device__ __forceinline__ uint32_t bfpack(__nv_bfloat16 lo, __nv_bfloat16 hi) {
    uint32_t l = __bfloat16_as_ushort(lo);
    uint32_t h = __bfloat16_as_ushort(hi);
    return l | (h << 16);
}
__device__ __forceinline__ void bfsplit2(float x0, float x1,
                                         uint32_t& hi, uint32_t& lo) {
    __nv_bfloat16 h0 = __float2bfloat16_rn(x0);
    __nv_bfloat16 h1 = __float2bfloat16_rn(x1);
    hi = bfpack(h0, h1);
    __nv_bfloat16 l0 = __float2bfloat16_rn(x0 - __bfloat162float(h0));
    __nv_bfloat16 l1 = __float2bfloat16_rn(x1 - __bfloat162float(h1));
    lo = bfpack(l0, l1);
}
__device__ __forceinline__ float4 ld_guard4(const float* p, int kg, int K) {
    if (kg + 4 <= K) return *(const float4*)p;
    float4 v;
    v.x = (kg     < K) ? p[0] : 0.f;
    v.y = (kg + 1 < K) ? p[1] : 0.f;
    v.z = (kg + 2 < K) ? p[2] : 0.f;
    v.w = (kg + 3 < K) ? p[3] : 0.f;
    return v;
}
__device__ __forceinline__ float fast_sigmoid(float x) {
    return __fdividef(1.f, 1.f + __expf(-x));
}
__device__ __forceinline__ float fast_tanh(float x) {
    return __fdividef(2.f, 1.f + __expf(-2.f * x)) - 1.f;
}

// ---------------- 3xBF16 tensor-core GEMM with ldmatrix fragments ----------
#define GEMM_SMEM (4 * 2 * 128 * 12 * 4)     // 49152 B
__global__ __launch_bounds__(256, 2) void gemm_bf16x3(
    const float* __restrict__ A, const float* __restrict__ W,
    const float* __restrict__ bias, float* __restrict__ C,
    int M, int N, int K, const int* __restrict__ lens, int T)
{
    extern __shared__ uint32_t dsm[];
    const int AH = 0, AL = 2*128*12, WH = 2*AL, WL = 3*AL;
    __shared__ int s_any;

    const int n0 = blockIdx.x * 128;
    const int m0 = blockIdx.y * 128;
    const int tid = threadIdx.x;

    if (lens) {
        if (tid == 0) {
            int any = 0;
            for (int r = 0; r < 128; r++) {
                int row = m0 + r;
                if (row % T < lens[row / T]) { any = 1; break; }
            }
            s_any = any;
        }
        __syncthreads();
        if (!s_any) return;
    }

    const int wid  = tid / 32, lane = tid % 32;
    const int wm   = (wid / 4) * 64;
    const int wn   = (wid % 4) * 32;
    const int gid  = lane >> 2, tig = lane & 3;
    const int quad = lane >> 3, lrow = lane & 7;
    const int arow = ((quad & 1) << 3) + lrow;
    const int ak2  = (quad >> 1) * 4;
    const int wrow = ((quad >> 1) << 3) + lrow;
    const int wk2  = (quad & 1) * 4;
    const uint32_t sbase = (uint32_t)__cvta_generic_to_shared(dsm);
    const int niter = (K + 15) >> 4;

    const int c0r = tid >> 2,          c0k = (tid & 3) * 4;
    const int c1r = (tid + 256) >> 2,  c1k = ((tid + 256) & 3) * 4;

    float acc[4][4][4];
#pragma unroll
    for (int i = 0; i < 4; i++)
#pragma unroll
        for (int j = 0; j < 4; j++)
#pragma unroll
            for (int c = 0; c < 4; c++) acc[i][j][c] = 0.f;

    float4 ra0, ra1, rw0, rw1;
    ra0 = ld_guard4(A + (size_t)(m0 + c0r) * K + c0k, c0k, K);
    ra1 = ld_guard4(A + (size_t)(m0 + c1r) * K + c1k, c1k, K);
    rw0 = ld_guard4(W + (size_t)(n0 + c0r) * K + c0k, c0k, K);
    rw1 = ld_guard4(W + (size_t)(n0 + c1r) * K + c1k, c1k, K);

    for (int kt = 0; kt < niter; kt++) {
        const int buf = kt & 1;
        const int bo = buf * 128;
        {
            uint32_t h0, l0, h1, l1;
            int k2 = c0k >> 1;
            int r0i = (bo + c0r) * 12, r1i = (bo + c1r) * 12;
            bfsplit2(ra0.x, ra0.y, h0, l0); bfsplit2(ra0.z, ra0.w, h1, l1);
            *(uint2*)&dsm[AH + r0i + k2] = make_uint2(h0, h1);
            *(uint2*)&dsm[AL + r0i + k2] = make_uint2(l0, l1);
            bfsplit2(rw0.x, rw0.y, h0, l0); bfsplit2(rw0.z, rw0.w, h1, l1);
            *(uint2*)&dsm[WH + r0i + k2] = make_uint2(h0, h1);
            *(uint2*)&dsm[WL + r0i + k2] = make_uint2(l0, l1);
            k2 = c1k >> 1;
            bfsplit2(ra1.x, ra1.y, h0, l0); bfsplit2(ra1.z, ra1.w, h1, l1);
            *(uint2*)&dsm[AH + r1i + k2] = make_uint2(h0, h1);
            *(uint2*)&dsm[AL + r1i + k2] = make_uint2(l0, l1);
            bfsplit2(rw1.x, rw1.y, h0, l0); bfsplit2(rw1.z, rw1.w, h1, l1);
            *(uint2*)&dsm[WH + r1i + k2] = make_uint2(h0, h1);
            *(uint2*)&dsm[WL + r1i + k2] = make_uint2(l0, l1);
        }
        __syncthreads();

        if (kt + 1 < niter) {
            const int kg = (kt + 1) * 16;
            ra0 = ld_guard4(A + (size_t)(m0 + c0r) * K + kg + c0k, kg + c0k, K);
            ra1 = ld_guard4(A + (size_t)(m0 + c1r) * K + kg + c1k, kg + c1k, K);
            rw0 = ld_guard4(W + (size_t)(n0 + c0r) * K + kg + c0k, kg + c0k, K);
            rw1 = ld_guard4(W + (size_t)(n0 + c1r) * K + kg + c1k, kg + c1k, K);
        }

        uint32_t bh[4][2], bl[4][2];
#pragma unroll
        for (int jp = 0; jp < 2; jp++) {
            uint32_t r[4];
            uint32_t a = sbase + (WH + (bo + wn + jp * 16 + wrow) * 12 + wk2) * 4;
            ldsm_x4(r, a);
            bh[jp*2][0] = r[0]; bh[jp*2][1] = r[1];
            bh[jp*2+1][0] = r[2]; bh[jp*2+1][1] = r[3];
            ldsm_x4(r, a + (WL - WH) * 4);
            bl[jp*2][0] = r[0]; bl[jp*2][1] = r[1];
            bl[jp*2+1][0] = r[2]; bl[jp*2+1][1] = r[3];
        }
#pragma unroll
        for (int mi = 0; mi < 4; mi++) {
            uint32_t ah[4], al[4];
            uint32_t a = sbase + (AH + (bo + wm + mi * 16 + arow) * 12 + ak2) * 4;
            ldsm_x4(ah, a);
            ldsm_x4(al, a + (AL - AH) * 4);
#pragma unroll
            for (int j = 0; j < 4; j++) {
                mma_bf16(acc[mi][j], ah, bh[j]);
                mma_bf16(acc[mi][j], al, bh[j]);
                mma_bf16(acc[mi][j], ah, bl[j]);
            }
        }
    }

#pragma unroll
    for (int i = 0; i < 4; i++) {
#pragma unroll
        for (int j = 0; j < 4; j++) {
            int col = n0 + wn + j * 8 + tig * 2;
            float b0 = bias[col], b1 = bias[col + 1];
            int r0g = m0 + wm + i * 16 + gid;
            *(float2*)&C[(size_t)r0g * N + col] =
                make_float2(acc[i][j][0] + b0, acc[i][j][1] + b1);
            *(float2*)&C[(size_t)(r0g + 8) * N + col] =
                make_float2(acc[i][j][2] + b0, acc[i][j][3] + b1);
        }
    }
}

// ---------------- software grid barrier ----------------
__device__ __forceinline__ void grid_sync(unsigned* bar, int ncta, unsigned* gen)
{
    __syncthreads();
    if (threadIdx.x == 0) {
        unsigned target = *gen + 1u;
        __threadfence();
        unsigned arr = atomicAdd(&bar[0], 1u);
        if (arr == (unsigned)(ncta - 1)) {
            atomicExch(&bar[0], 0u);
            __threadfence();
            atomicExch(&bar[1], target);
        } else {
            while (*(volatile unsigned*)&bar[1] < target) { }
        }
        __threadfence();
        *gen = target;
    }
    __syncthreads();
}

// ---------------- persistent GRU: bf16x3 LDSM phase1, valid-only phase2 ----
// W split hi/lo into smem ONCE; h staged hi/lo per step (valid prefix).
// smem u32 layout: WHs[4][96][12] @0 (4608) | WLs @4608 | HHs[4][128][12]
// @9216 (6144) | HLs @15360.  Total 21504 u32 = 86016 B (2 CTAs/SM ok).
#define GRU_SMEM (21504 * 4)
template<int H, int G3, int T, int NCT, int KS>
__global__ __launch_bounds__(256, 2) void gru_persistent(
    const float* __restrict__ xp, const float* __restrict__ w_hh,
    const float* __restrict__ b_hh, float* __restrict__ hbuf,
    float* __restrict__ part, float* __restrict__ out,
    const int* __restrict__ perm, const int* __restrict__ cnt,
    unsigned* __restrict__ bar)
{
    constexpr int KC = 64;
    constexpr int NCTA = 2 * NCT * KS;
    constexpr int H2 = H / 2;
    extern __shared__ uint32_t sm[];
    const int WHo = 0, WLo = 4608, HHo = 9216, HLo = 15360;

    const int cta = blockIdx.x;
    const int d   = cta / (NCT * KS);
    const int ct  = (cta % (NCT * KS)) / KS;
    const int ks  = cta % KS;
    const int c0  = ct * 96;
    const int k0  = ks * KC;
    const int tid = threadIdx.x;
    const int wid = tid / 32, lane = tid % 32;
    const int gid = lane >> 2, tig = lane & 3;
    const int wm  = (wid >> 1) * 32;
    const int wn  = (wid & 1) * 48;
    const int quad = lane >> 3, lrow = lane & 7;
    const int arow = ((quad & 1) << 3) + lrow;
    const int ak2  = (quad >> 1) * 4;
    const int wrow = ((quad >> 1) << 3) + lrow;
    const int wk2  = (quad & 1) * 4;
    const uint32_t sbase = (uint32_t)__cvta_generic_to_shared(sm);

    // W tile -> smem bf16 hi/lo, once. WHs[slab][c][k2l]
    for (int e = tid; e < 96 * 32; e += 256) {
        int c = e >> 5, k2 = e & 31;
        int slab = k2 >> 3, k2l = k2 & 7;
        const float* wp = w_hh + ((size_t)d * G3 + c0 + c) * H + k0 + 2 * k2;
        uint32_t h, l;
        bfsplit2(wp[0], wp[1], h, l);
        sm[WHo + slab * 1152 + c * 12 + k2l] = h;
        sm[WLo + slab * 1152 + c * 12 + k2l] = l;
    }
    __syncthreads();

    unsigned gen = 0;
    const int nth = NCTA * 256;

    for (int t = 0; t < T; t++) {
        const int cnt0 = cnt[t];
        const int cnt1 = cnt[T - 1 - t];
        const int cd   = (d == 0) ? cnt0 : cnt1;
        const int rc   = (cd + 31) & ~31;

        // stage h slice hi/lo: HHs[slab][row][k2l]
        for (int e = tid; e < rc * 16; e += 256) {
            int row = e >> 4, k4 = e & 15;
            int slab = k4 >> 2, k2s = (k4 & 3) * 2;
            float4 v = *(const float4*)&hbuf[((size_t)d * B + row) * H + k0 + k4 * 4];
            uint32_t h0, l0, h1, l1;
            bfsplit2(v.x, v.y, h0, l0);
            bfsplit2(v.z, v.w, h1, l1);
            int o = slab * 1536 + row * 12 + k2s;
            *(uint2*)&sm[HHo + o] = make_uint2(h0, h1);
            *(uint2*)&sm[HLo + o] = make_uint2(l0, l1);
        }
        __syncthreads();

        if (wm < cd) {
            float acc[2][6][4];
#pragma unroll
            for (int i = 0; i < 2; i++)
#pragma unroll
                for (int j = 0; j < 6; j++)
#pragma unroll
                    for (int c = 0; c < 4; c++) acc[i][j][c] = 0.f;

#pragma unroll
            for (int s = 0; s < 4; s++) {
                uint32_t bh[6][2], bl[6][2];
#pragma unroll
                for (int jp = 0; jp < 3; jp++) {
                    uint32_t r[4];
                    uint32_t a = sbase + (WHo + s * 1152 + (wn + jp * 16 + wrow) * 12 + wk2) * 4;
                    ldsm_x4(r, a);
                    bh[jp*2][0] = r[0]; bh[jp*2][1] = r[1];
                    bh[jp*2+1][0] = r[2]; bh[jp*2+1][1] = r[3];
                    ldsm_x4(r, a + (WLo - WHo) * 4);
                    bl[jp*2][0] = r[0]; bl[jp*2][1] = r[1];
                    bl[jp*2+1][0] = r[2]; bl[jp*2+1][1] = r[3];
                }
#pragma unroll
                for (int mi = 0; mi < 2; mi++) {
                    uint32_t ah[4], al[4];
                    uint32_t a = sbase + (HHo + s * 1536 + (wm + mi * 16 + arow) * 12 + ak2) * 4;
                    ldsm_x4(ah, a);
                    ldsm_x4(al, a + (HLo - HHo) * 4);
#pragma unroll
                    for (int j = 0; j < 6; j++) {
                        mma_bf16(acc[mi][j], ah, bh[j]);
                        mma_bf16(acc[mi][j], al, bh[j]);
                        mma_bf16(acc[mi][j], ah, bl[j]);
                    }
                }
            }
#pragma unroll
            for (int mi = 0; mi < 2; mi++) {
                int r = wm + mi * 16 + gid;
#pragma unroll
                for (int j = 0; j < 6; j++) {
                    int col = c0 + wn + j * 8 + tig * 2;
                    float* p0 = part + (((size_t)ks * 2 + d) * B + r) * G3 + col;
                    float* p1 = part + (((size_t)ks * 2 + d) * B + r + 8) * G3 + col;
                    *(float2*)p0 = make_float2(acc[mi][j][0], acc[mi][j][1]);
                    *(float2*)p1 = make_float2(acc[mi][j][2], acc[mi][j][3]);
                }
            }
        }
        grid_sync(bar, NCTA, &gen);

        // phase2: valid elements only, 2 consecutive j per thread (float2 IO)
        const int n0e = cnt0 * H2;
        const int total = n0e + cnt1 * H2;
        for (int it = cta * 256 + tid; it < total; it += nth) {
            int dd = (it >= n0e);
            int loc = dd ? (it - n0e) : it;
            int rr = loc / H2, j = (loc % H2) * 2;
            int te = dd ? (T - 1 - t) : t;
            int bo = perm[rr];
            float2 hold = *(const float2*)&hbuf[((size_t)dd * B + rr) * H + j];
            float2 hpr = make_float2(0.f, 0.f);
            float2 hpz = make_float2(0.f, 0.f);
            float2 hpn = make_float2(0.f, 0.f);
#pragma unroll
            for (int s = 0; s < KS; s++) {
                const float* pb = part + (((size_t)s * 2 + dd) * B + rr) * G3;
                float2 v;
                v = *(const float2*)(pb + j);         hpr.x += v.x; hpr.y += v.y;
                v = *(const float2*)(pb + H + j);     hpz.x += v.x; hpz.y += v.y;
                v = *(const float2*)(pb + 2 * H + j); hpn.x += v.x; hpn.y += v.y;
            }
            const float* bb = b_hh + (size_t)dd * G3;
            float2 br = *(const float2*)(bb + j);
            float2 bz = *(const float2*)(bb + H + j);
            float2 bn = *(const float2*)(bb + 2 * H + j);
            const float* xr = xp + ((size_t)bo * T + te) * (2 * G3) + (size_t)dd * G3;
            float2 xrv = *(const float2*)(xr + j);
            float2 xzv = *(const float2*)(xr + H + j);
            float2 xnv = *(const float2*)(xr + 2 * H + j);
            float rg0 = fast_sigmoid(xrv.x + hpr.x + br.x);
            float rg1 = fast_sigmoid(xrv.y + hpr.y + br.y);
            float zg0 = fast_sigmoid(xzv.x + hpz.x + bz.x);
            float zg1 = fast_sigmoid(xzv.y + hpz.y + bz.y);
            float ng0 = fast_tanh(xnv.x + rg0 * (hpn.x + bn.x));
            float ng1 = fast_tanh(xnv.y + rg1 * (hpn.y + bn.y));
            float2 hnew = make_float2((1.f - zg0) * ng0 + zg0 * hold.x,
                                      (1.f - zg1) * ng1 + zg1 * hold.y);
            *(float2*)&hbuf[((size_t)dd * B + rr) * H + j] = hnew;
            *(float2*)&out[((size_t)bo * T + te) * (2 * H) + dd * H + j] = hnew;
        }
        grid_sync(bar, NCTA, &gen);
    }
}

// ---------------- segment means ----------------
__global__ __launch_bounds__(256) void seg_mean_kernel(
    const float* __restrict__ vf, const float* __restrict__ loc,
    const int* __restrict__ v_len,
    float* __restrict__ lmean, float* __restrict__ rmean, float* __restrict__ cat)
{
    const int b = blockIdx.x;
    const int col = blockIdx.y * 256 + threadIdx.x;
    const int vl = v_len[b];
    const float scale = (float)(vl - 1);
    const float l0 = loc[b * 2], l1 = loc[b * 2 + 1];
    const int cond = (l0 <= l1);
    const float lhi = cond ? l0 : 0.f;
    const float rlo = cond ? l1 : 1.f;
    const int lend   = (int)floorf(lhi * scale);
    const int rstart = (int)floorf(rlo * scale);
    const int rend   = vl - 1;
    const int ok_l = (0 <= lend);
    const int ok_r = (rstart <= rend);

    float ls = 0.f, rs = 0.f, gs = 0.f;
    for (int t = 0; t < vl; t++) {
        float v = vf[((size_t)b * TV + t) * 1024 + col];
        gs += v;
        if (ok_l && t <= lend) ls += v;
        if (ok_r && t >= rstart) rs += v;
    }
    float lcnt = ok_l ? (float)(lend + 1) : 1.f;
    float rcnt = ok_r ? (float)(rend - rstart + 1) : 1.f;
    if (lcnt < 1.f) lcnt = 1.f;
    if (rcnt < 1.f) rcnt = 1.f;
    lmean[b * 1024 + col] = ls / lcnt;
    rmean[b * 1024 + col] = rs / rcnt;
    cat[(size_t)b * NCAT + 512 + col] = gs / (float)vl;
}

// ---------------- gather sen_fea ----------------
__global__ void gather_senfea(const float* __restrict__ words,
                              const int* __restrict__ lens,
                              float* __restrict__ out_sf, float* __restrict__ cat)
{
    const int b = blockIdx.x;
    const int t = lens[b] - 1;
    for (int c = threadIdx.x; c < 2 * SHID; c += blockDim.x) {
        float v = words[((size_t)b * TS + t) * (2 * SHID) + c];
        out_sf[(size_t)b * (2 * SHID) + c] = v;
        cat[(size_t)b * NCAT + c] = v;
    }
}

// ---------------- small GEMM with epilogue ----------------
__global__ __launch_bounds__(256) void gemm_small(
    const float* __restrict__ A, const float* __restrict__ W,
    const float* __restrict__ bias, const float* __restrict__ mul, int mulLd,
    float* __restrict__ C, int ldC, int M, int N, int K, int relu)
{
    const int n0 = blockIdx.x * 32, m0 = blockIdx.y * 32;
    __shared__ __align__(16) float As[32][34];
    __shared__ __align__(16) float Wsm[32][34];
    const int tid = threadIdx.x, ty = tid / 16, tx = tid % 16;
    float acc[2][2] = {{0.f, 0.f}, {0.f, 0.f}};

    for (int k0 = 0; k0 < K; k0 += 32) {
        for (int e = tid; e < 1024; e += 256) {
            int r = e / 32, k = e % 32;
            int kg = k0 + k;
            As[k][r]  = (kg < K) ? A[(size_t)(m0 + r) * K + kg] : 0.f;
            Wsm[k][r] = (kg < K) ? W[(size_t)(n0 + r) * K + kg] : 0.f;
        }
        __syncthreads();
#pragma unroll
        for (int k = 0; k < 32; k++) {
            float2 av = *(const float2*)&As[k][ty * 2];
            float2 wv = *(const float2*)&Wsm[k][tx * 2];
            acc[0][0] += av.x * wv.x;  acc[0][1] += av.x * wv.y;
            acc[1][0] += av.y * wv.x;  acc[1][1] += av.y * wv.y;
        }
        __syncthreads();
    }
#pragma unroll
    for (int i = 0; i < 2; i++) {
        int m = m0 + ty * 2 + i;
#pragma unroll
        for (int j = 0; j < 2; j++) {
            int n = n0 + tx * 2 + j;
            float v = acc[i][j] + bias[n];
            if (mul) v *= mul[(size_t)m * mulLd + n];
            if (relu) v = fmaxf(v, 0.f);
            C[(size_t)m * ldC + n] = v;
        }
    }
}

// ---------------- launch ----------------
extern "C" void kernel_launch(void* const* d_in, const int* in_sizes, int n_in,
                              void* d_out, int out_size)
{
    const float* gv     = (const float*)d_in[1];
    const float* sen    = (const float*)d_in[2];
    const float* loc    = (const float*)d_in[5];
    const int*   lens   = (const int*)  d_in[6];
    const int*   v_len  = (const int*)  d_in[7];
    const float* v_w_ih = (const float*)d_in[8];
    const float* v_w_hh = (const float*)d_in[9];
    const float* v_b_ih = (const float*)d_in[10];
    const float* v_b_hh = (const float*)d_in[11];
    const float* s_w_ih = (const float*)d_in[12];
    const float* s_w_hh = (const float*)d_in[13];
    const float* s_b_ih = (const float*)d_in[14];
    const float* s_b_hh = (const float*)d_in[15];
    const float* fc1_w  = (const float*)d_in[16];
    const float* fc1_b  = (const float*)d_in[17];
    const float* fc2_w  = (const float*)d_in[18];
    const float* fc2_b  = (const float*)d_in[19];
    const float* fc3_w  = (const float*)d_in[20];
    const float* fc3_b  = (const float*)d_in[21];
    const float* fc4_w  = (const float*)d_in[22];
    const float* fc4_b  = (const float*)d_in[23];

    float* out    = (float*)d_out;
    float* out_vf = out;
    float* out_sf = out + VF_ELEMS;
    float* out_ft = out + VF_ELEMS + SF_ELEMS;

    float *xp_v, *xp_s, *h_v, *h_s, *part_v, *part_s, *words;
    float *lmean, *rmean, *cat, *sproj;
    int *perm_v, *lenp_v, *perm_s, *lenp_s, *cnt_v, *cnt_s;
    unsigned* bar;
    cudaGetSymbolAddress((void**)&xp_v,   g_xp_v);
    cudaGetSymbolAddress((void**)&xp_s,   g_xp_s);
    cudaGetSymbolAddress((void**)&h_v,    g_h_v);
    cudaGetSymbolAddress((void**)&h_s,    g_h_s);
    cudaGetSymbolAddress((void**)&part_v, g_part_v);
    cudaGetSymbolAddress((void**)&part_s, g_part_s);
    cudaGetSymbolAddress((void**)&words,  g_words);
    cudaGetSymbolAddress((void**)&lmean,  g_lmean);
    cudaGetSymbolAddress((void**)&rmean,  g_rmean);
    cudaGetSymbolAddress((void**)&cat,    g_cat);
    cudaGetSymbolAddress((void**)&sproj,  g_sproj);
    cudaGetSymbolAddress((void**)&perm_v, g_perm_v);
    cudaGetSymbolAddress((void**)&lenp_v, g_lenp_v);
    cudaGetSymbolAddress((void**)&perm_s, g_perm_s);
    cudaGetSymbolAddress((void**)&lenp_s, g_lenp_s);
    cudaGetSymbolAddress((void**)&cnt_v,  g_cnt_v);
    cudaGetSymbolAddress((void**)&cnt_s,  g_cnt_s);
    cudaGetSymbolAddress((void**)&bar,    g_bar);

    cudaFuncSetAttribute(gru_persistent<512, 1536, 256, 16, 8>,
                         cudaFuncAttributeMaxDynamicSharedMemorySize, GRU_SMEM);
    cudaFuncSetAttribute(gru_persistent<256, 768, 40, 8, 4>,
                         cudaFuncAttributeMaxDynamicSharedMemorySize, GRU_SMEM);
    cudaFuncSetAttribute(gemm_bf16x3,
                         cudaFuncAttributeMaxDynamicSharedMemorySize, GEMM_SMEM);

    // 1. sort + counts + zero h + zero visual output region
    sort_init_kernel<<<1, 128>>>(v_len, lens, perm_v, lenp_v, perm_s, lenp_s,
                                 cnt_v, cnt_s, bar);
    zero_h_kernel<<<(2*B*VHID + 255) / 256, 256>>>(h_v, h_s);
    zero_out_kernel<<<(int)(VF_ELEMS/4 + 255) / 256, 256>>>((float4*)out_vf,
                                                            (int)(VF_ELEMS/4));

    // 2. input projections (3xBF16, ldmatrix fragments)
    gemm_bf16x3<<<dim3(3072/128, (B*TV)/128), 256, GEMM_SMEM>>>(
        gv,  v_w_ih, v_b_ih, xp_v, B*TV, 3072, VIN, v_len, TV);
    gemm_bf16x3<<<dim3(1536/128, (B*TS)/128), 256, GEMM_SMEM>>>(
        sen, s_w_ih, s_b_ih, xp_s, B*TS, 1536, SIN, lens, TS);

    // 3. persistent visual GRU (bf16x3 LDSM phase1)
    gru_persistent<512, 1536, 256, 16, 8><<<256, 256, GRU_SMEM>>>(
        xp_v, v_w_hh, v_b_hh, h_v, part_v, out_vf, perm_v, cnt_v, bar);

    // 4. persistent sentence GRU
    gru_persistent<256, 768, 40, 8, 4><<<64, 256, GRU_SMEM>>>(
        xp_s, s_w_hh, s_b_hh, h_s, part_s, words, perm_s, cnt_s, bar + 2);

    // 5. sen_fea gather
    gather_senfea<<<B, 256>>>(words, lens, out_sf, cat);

    // 6. segment means + global mean
    seg_mean_kernel<<<dim3(B, 4), 256>>>(out_vf, loc, v_len, lmean, rmean, cat);

    // 7. FC stack
    gemm_small<<<dim3(LCROSS/32, B/32), 256>>>(out_sf, fc2_w, fc2_b, nullptr, 0,
                                               sproj, LCROSS, B, LCROSS, 2*SHID, 0);
    gemm_small<<<dim3(LCROSS/32, B/32), 256>>>(lmean, fc1_w, fc1_b, sproj, LCROSS,
                                               cat + 1536, NCAT, B, LCROSS, 2*VHID, 1);
    gemm_small<<<dim3(LCROSS/32, B/32), 256>>>(rmean, fc1_w, fc1_b, sproj, LCROSS,
                                               cat + 2048, NCAT, B, LCROSS, 2*VHID, 1);
    gemm_small<<<dim3(NLOC/32, B/32), 256>>>(loc, fc3_w, fc3_b, nullptr, 0,
                                             cat + 2560, NCAT, B, NLOC, 2, 1);
    gemm_small<<<dim3(NFEAT/32, B/32), 256>>>(cat, fc4_w, fc4_b, nullptr, 0,
                                              out_ft, NFEAT, B, NFEAT, NCAT, 1);
}

// round 13
// speedup vs baseline: 1.9029x; 1.0910x over previous
#include <cuda_runtime.h>
#include <cuda_bf16.h>
#include <math.h>
#include <stdint.h>

// ---------------- problem constants ----------------
#define B        128
#define TV       256
#define TS       40
#define VIN      1024
#define VHID     512
#define SIN      300
#define SHID     256
#define NCAT     2624
#define NFEAT    1024
#define LCROSS   512
#define NLOC     64

#define VF_ELEMS   ((size_t)B*TV*2*VHID)
#define SF_ELEMS   ((size_t)B*2*SHID)

// ---------------- scratch (__device__ globals) ----------------
__device__ float g_xp_v[(size_t)B*TV*3072];
__device__ float g_xp_s[(size_t)B*TS*1536];
__device__ float g_h_v[2*B*VHID];
__device__ float g_h_s[2*B*SHID];
__device__ float g_part_v[8*2*B*1536];
__device__ float g_part_s[4*2*B*768];
__device__ float g_words[(size_t)B*TS*2*SHID];
__device__ float g_lmean[B*1024];
__device__ float g_rmean[B*1024];
__device__ float g_cat[B*NCAT];
__device__ float g_sproj[B*LCROSS];
__device__ int   g_perm_v[B], g_lenp_v[B];
__device__ int   g_perm_s[B], g_lenp_s[B];
__device__ int   g_cnt_v[TV], g_cnt_s[TS];
__device__ int   g_ridx_v[B*TV], g_ridx_s[B*TS]; // compacted valid rows, -1 pad
__device__ int   g_nv[2];                        // [0]=valid rows v, [1]=s
__device__ unsigned g_bar[4];

// ---------------- init ----------------
__global__ void sort_init_kernel(const int* __restrict__ v_len,
                                 const int* __restrict__ lens,
                                 int* pv, int* lv, int* ps, int* ls,
                                 int* cv, int* cs,
                                 int* ridxv, int* ridxs, int* nv,
                                 unsigned* bar)
{
    int i = threadIdx.x;
    if (i < 4) bar[i] = 0u;

    // pad-fill compacted row lists
    for (int e = i; e < B*TV; e += 128) ridxv[e] = -1;
    for (int e = i; e < B*TS; e += 128) ridxs[e] = -1;
    __syncthreads();

    // length-desc permutation
    int a = v_len[i], rank = 0;
    for (int j = 0; j < B; j++) {
        int c = v_len[j];
        rank += (c > a) || (c == a && j < i);
    }
    pv[rank] = i; lv[rank] = a;
    a = lens[i]; rank = 0;
    for (int j = 0; j < B; j++) {
        int c = lens[j];
        rank += (c > a) || (c == a && j < i);
    }
    ps[rank] = i; ls[rank] = a;

    // per-step valid counts
    for (int t = i; t < TV; t += 128) {
        int c = 0;
        for (int j = 0; j < B; j++) c += (v_len[j] > t);
        cv[t] = c;
    }
    for (int t = i; t < TS; t += 128) {
        int c = 0;
        for (int j = 0; j < B; j++) c += (lens[j] > t);
        cs[t] = c;
    }

    // compacted (b,t) row lists (thread i = batch i)
    int offv = 0, offs = 0;
    for (int j = 0; j < i; j++) { offv += v_len[j]; offs += lens[j]; }
    int lv_i = v_len[i], ls_i = lens[i];
    for (int t = 0; t < lv_i; t++) ridxv[offv + t] = i * TV + t;
    for (int t = 0; t < ls_i; t++) ridxs[offs + t] = i * TS + t;
    if (i == B - 1) {
        nv[0] = offv + lv_i;
        nv[1] = offs + ls_i;
    }
}

__global__ void zero_h_kernel(float* hv, float* hs) {
    int i = blockIdx.x * blockDim.x + threadIdx.x;
    if (i < 2*B*VHID) hv[i] = 0.f;
    if (i < 2*B*SHID) hs[i] = 0.f;
}

__global__ void zero_out_kernel(float4* p, int n4) {
    int i = blockIdx.x * blockDim.x + threadIdx.x;
    if (i < n4) p[i] = make_float4(0.f, 0.f, 0.f, 0.f);
}

// ---------------- numeric helpers ----------------
__device__ __forceinline__ void mma_bf16(float* d, const uint32_t* a, const uint32_t* b) {
    asm volatile(
        "mma.sync.aligned.m16n8k16.row.col.f32.bf16.bf16.f32 "
        "{%0,%1,%2,%3}, {%4,%5,%6,%7}, {%8,%9}, {%0,%1,%2,%3};"
        : "+f"(d[0]), "+f"(d[1]), "+f"(d[2]), "+f"(d[3])
        : "r"(a[0]), "r"(a[1]), "r"(a[2]), "r"(a[3]), "r"(b[0]), "r"(b[1]));
}
__device__ __forceinline__ void ldsm_x4(uint32_t* r, uint32_t saddr) {
    asm volatile("ldmatrix.sync.aligned.m8n8.x4.shared.b16 {%0,%1,%2,%3}, [%4];"
                 : "=r"(r[0]), "=r"(r[1]), "=r"(r[2]), "=r"(r[3]) : "r"(saddr));
}
__device__ __forceinline__ uint32_t bfpack(__nv_bfloat16 lo, __nv_bfloat16 hi) {
    uint32_t l = __bfloat16_as_ushort(lo);
    uint32_t h = __bfloat16_as_ushort(hi);
    return l | (h << 16);
}
__device__ __forceinline__ void bfsplit2(float x0, float x1,
                                         uint32_t& hi, uint32_t& lo) {
    __nv_bfloat16 h0 = __float2bfloat16_rn(x0);
    __nv_bfloat16 h1 = __float2bfloat16_rn(x1);
    hi = bfpack(h0, h1);
    __nv_bfloat16 l0 = __float2bfloat16_rn(x0 - __bfloat162float(h0));
    __nv_bfloat16 l1 = __float2bfloat16_rn(x1 - __bfloat162float(h1));
    lo = bfpack(l0, l1);
}
__device__ __forceinline__ float4 ld_guard4(const float* p, int kg, int K) {
    if (kg + 4 <= K) return *(const float4*)p;
    float4 v;
    v.x = (kg     < K) ? p[0] : 0.f;
    v.y = (kg + 1 < K) ? p[1] : 0.f;
    v.z = (kg + 2 < K) ? p[2] : 0.f;
    v.w = (kg + 3 < K) ? p[3] : 0.f;
    return v;
}
__device__ __forceinline__ float fast_sigmoid(float x) {
    return __fdividef(1.f, 1.f + __expf(-x));
}
__device__ __forceinline__ float fast_tanh(float x) {
    return __fdividef(2.f, 1.f + __expf(-2.f * x)) - 1.f;
}

// ---------------- 3xBF16 tensor-core GEMM, row-compacted ----------
// A rows gathered via ridx (valid (b,t) rows only, -1 pad); C scattered back.
#define GEMM_SMEM (4 * 2 * 128 * 12 * 4)     // 49152 B
__global__ __launch_bounds__(256, 2) void gemm_bf16x3(
    const float* __restrict__ A, const float* __restrict__ W,
    const float* __restrict__ bias, float* __restrict__ C,
    const int* __restrict__ ridx, const int* __restrict__ nvp,
    int N, int K)
{
    extern __shared__ uint32_t dsm[];
    const int AH = 0, AL = 2*128*12, WH = 2*AL, WL = 3*AL;
    __shared__ int sridx[128];

    const int n0 = blockIdx.x * 128;
    const int m0 = blockIdx.y * 128;
    const int tid = threadIdx.x;

    const int nv = *nvp;
    if (m0 >= nv) return;

    if (tid < 128) sridx[tid] = ridx[m0 + tid];
    __syncthreads();

    const int wid  = tid / 32, lane = tid % 32;
    const int wm   = (wid / 4) * 64;
    const int wn   = (wid % 4) * 32;
    const int gid  = lane >> 2, tig = lane & 3;
    const int quad = lane >> 3, lrow = lane & 7;
    const int arow = ((quad & 1) << 3) + lrow;
    const int ak2  = (quad >> 1) * 4;
    const int wrow = ((quad >> 1) << 3) + lrow;
    const int wk2  = (quad & 1) * 4;
    const uint32_t sbase = (uint32_t)__cvta_generic_to_shared(dsm);
    const int niter = (K + 15) >> 4;

    const int c0r = tid >> 2,          c0k = (tid & 3) * 4;
    const int c1r = (tid + 256) >> 2,  c1k = ((tid + 256) & 3) * 4;
    const int rm0 = sridx[c0r] < 0 ? 0 : sridx[c0r];
    const int rm1 = sridx[c1r] < 0 ? 0 : sridx[c1r];

    float acc[4][4][4];
#pragma unroll
    for (int i = 0; i < 4; i++)
#pragma unroll
        for (int j = 0; j < 4; j++)
#pragma unroll
            for (int c = 0; c < 4; c++) acc[i][j][c] = 0.f;

    float4 ra0, ra1, rw0, rw1;
    ra0 = ld_guard4(A + (size_t)rm0 * K + c0k, c0k, K);
    ra1 = ld_guard4(A + (size_t)rm1 * K + c1k, c1k, K);
    rw0 = ld_guard4(W + (size_t)(n0 + c0r) * K + c0k, c0k, K);
    rw1 = ld_guard4(W + (size_t)(n0 + c1r) * K + c1k, c1k, K);

    for (int kt = 0; kt < niter; kt++) {
        const int buf = kt & 1;
        const int bo = buf * 128;
        {
            uint32_t h0, l0, h1, l1;
            int k2 = c0k >> 1;
            int r0i = (bo + c0r) * 12, r1i = (bo + c1r) * 12;
            bfsplit2(ra0.x, ra0.y, h0, l0); bfsplit2(ra0.z, ra0.w, h1, l1);
            *(uint2*)&dsm[AH + r0i + k2] = make_uint2(h0, h1);
            *(uint2*)&dsm[AL + r0i + k2] = make_uint2(l0, l1);
            bfsplit2(rw0.x, rw0.y, h0, l0); bfsplit2(rw0.z, rw0.w, h1, l1);
            *(uint2*)&dsm[WH + r0i + k2] = make_uint2(h0, h1);
            *(uint2*)&dsm[WL + r0i + k2] = make_uint2(l0, l1);
            k2 = c1k >> 1;
            bfsplit2(ra1.x, ra1.y, h0, l0); bfsplit2(ra1.z, ra1.w, h1, l1);
            *(uint2*)&dsm[AH + r1i + k2] = make_uint2(h0, h1);
            *(uint2*)&dsm[AL + r1i + k2] = make_uint2(l0, l1);
            bfsplit2(rw1.x, rw1.y, h0, l0); bfsplit2(rw1.z, rw1.w, h1, l1);
            *(uint2*)&dsm[WH + r1i + k2] = make_uint2(h0, h1);
            *(uint2*)&dsm[WL + r1i + k2] = make_uint2(l0, l1);
        }
        __syncthreads();

        if (kt + 1 < niter) {
            const int kg = (kt + 1) * 16;
            ra0 = ld_guard4(A + (size_t)rm0 * K + kg + c0k, kg + c0k, K);
            ra1 = ld_guard4(A + (size_t)rm1 * K + kg + c1k, kg + c1k, K);
            rw0 = ld_guard4(W + (size_t)(n0 + c0r) * K + kg + c0k, kg + c0k, K);
            rw1 = ld_guard4(W + (size_t)(n0 + c1r) * K + kg + c1k, kg + c1k, K);
        }

        uint32_t bh[4][2], bl[4][2];
#pragma unroll
        for (int jp = 0; jp < 2; jp++) {
            uint32_t r[4];
            uint32_t a = sbase + (WH + (bo + wn + jp * 16 + wrow) * 12 + wk2) * 4;
            ldsm_x4(r, a);
            bh[jp*2][0] = r[0]; bh[jp*2][1] = r[1];
            bh[jp*2+1][0] = r[2]; bh[jp*2+1][1] = r[3];
            ldsm_x4(r, a + (WL - WH) * 4);
            bl[jp*2][0] = r[0]; bl[jp*2][1] = r[1];
            bl[jp*2+1][0] = r[2]; bl[jp*2+1][1] = r[3];
        }
#pragma unroll
        for (int mi = 0; mi < 4; mi++) {
            uint32_t ah[4], al[4];
            uint32_t a = sbase + (AH + (bo + wm + mi * 16 + arow) * 12 + ak2) * 4;
            ldsm_x4(ah, a);
            ldsm_x4(al, a + (AL - AH) * 4);
#pragma unroll
            for (int j = 0; j < 4; j++) {
                mma_bf16(acc[mi][j], ah, bh[j]);
                mma_bf16(acc[mi][j], al, bh[j]);
                mma_bf16(acc[mi][j], ah, bl[j]);
            }
        }
    }

#pragma unroll
    for (int i = 0; i < 4; i++) {
        int lr0 = wm + i * 16 + gid;
        int g0 = sridx[lr0], g1 = sridx[lr0 + 8];
#pragma unroll
        for (int j = 0; j < 4; j++) {
            int col = n0 + wn + j * 8 + tig * 2;
            float b0 = bias[col], b1 = bias[col + 1];
            if (g0 >= 0)
                *(float2*)&C[(size_t)g0 * N + col] =
                    make_float2(acc[i][j][0] + b0, acc[i][j][1] + b1);
            if (g1 >= 0)
                *(float2*)&C[(size_t)g1 * N + col] =
                    make_float2(acc[i][j][2] + b0, acc[i][j][3] + b1);
        }
    }
}

// ---------------- software grid barrier ----------------
__device__ __forceinline__ void grid_sync(unsigned* bar, int ncta, unsigned* gen)
{
    __syncthreads();
    if (threadIdx.x == 0) {
        unsigned target = *gen + 1u;
        __threadfence();
        unsigned arr = atomicAdd(&bar[0], 1u);
        if (arr == (unsigned)(ncta - 1)) {
            atomicExch(&bar[0], 0u);
            __threadfence();
            atomicExch(&bar[1], target);
        } else {
            while (*(volatile unsigned*)&bar[1] < target) { }
        }
        __threadfence();
        *gen = target;
    }
    __syncthreads();
}

// ---------------- persistent GRU: bf16x3 LDSM phase1, valid-only phase2 ----
#define GRU_SMEM (21504 * 4)
template<int H, int G3, int T, int NCT, int KS>
__global__ __launch_bounds__(256, 2) void gru_persistent(
    const float* __restrict__ xp, const float* __restrict__ w_hh,
    const float* __restrict__ b_hh, float* __restrict__ hbuf,
    float* __restrict__ part, float* __restrict__ out,
    const int* __restrict__ perm, const int* __restrict__ cnt,
    unsigned* __restrict__ bar)
{
    constexpr int KC = 64;
    constexpr int NCTA = 2 * NCT * KS;
    constexpr int H2 = H / 2;
    extern __shared__ uint32_t sm[];
    const int WHo = 0, WLo = 4608, HHo = 9216, HLo = 15360;

    const int cta = blockIdx.x;
    const int d   = cta / (NCT * KS);
    const int ct  = (cta % (NCT * KS)) / KS;
    const int ks  = cta % KS;
    const int c0  = ct * 96;
    const int k0  = ks * KC;
    const int tid = threadIdx.x;
    const int wid = tid / 32, lane = tid % 32;
    const int gid = lane >> 2, tig = lane & 3;
    const int wm  = (wid >> 1) * 32;
    const int wn  = (wid & 1) * 48;
    const int quad = lane >> 3, lrow = lane & 7;
    const int arow = ((quad & 1) << 3) + lrow;
    const int ak2  = (quad >> 1) * 4;
    const int wrow = ((quad >> 1) << 3) + lrow;
    const int wk2  = (quad & 1) * 4;
    const uint32_t sbase = (uint32_t)__cvta_generic_to_shared(sm);

    for (int e = tid; e < 96 * 32; e += 256) {
        int c = e >> 5, k2 = e & 31;
        int slab = k2 >> 3, k2l = k2 & 7;
        const float* wp = w_hh + ((size_t)d * G3 + c0 + c) * H + k0 + 2 * k2;
        uint32_t h, l;
        bfsplit2(wp[0], wp[1], h, l);
        sm[WHo + slab * 1152 + c * 12 + k2l] = h;
        sm[WLo + slab * 1152 + c * 12 + k2l] = l;
    }
    __syncthreads();

    unsigned gen = 0;
    const int nth = NCTA * 256;

    for (int t = 0; t < T; t++) {
        const int cnt0 = cnt[t];
        const int cnt1 = cnt[T - 1 - t];
        const int cd   = (d == 0) ? cnt0 : cnt1;
        const int rc   = (cd + 31) & ~31;

        for (int e = tid; e < rc * 16; e += 256) {
            int row = e >> 4, k4 = e & 15;
            int slab = k4 >> 2, k2s = (k4 & 3) * 2;
            float4 v = *(const float4*)&hbuf[((size_t)d * B + row) * H + k0 + k4 * 4];
            uint32_t h0, l0, h1, l1;
            bfsplit2(v.x, v.y, h0, l0);
            bfsplit2(v.z, v.w, h1, l1);
            int o = slab * 1536 + row * 12 + k2s;
            *(uint2*)&sm[HHo + o] = make_uint2(h0, h1);
            *(uint2*)&sm[HLo + o] = make_uint2(l0, l1);
        }
        __syncthreads();

        if (wm < cd) {
            float acc[2][6][4];
#pragma unroll
            for (int i = 0; i < 2; i++)
#pragma unroll
                for (int j = 0; j < 6; j++)
#pragma unroll
                    for (int c = 0; c < 4; c++) acc[i][j][c] = 0.f;

#pragma unroll
            for (int s = 0; s < 4; s++) {
                uint32_t bh[6][2], bl[6][2];
#pragma unroll
                for (int jp = 0; jp < 3; jp++) {
                    uint32_t r[4];
                    uint32_t a = sbase + (WHo + s * 1152 + (wn + jp * 16 + wrow) * 12 + wk2) * 4;
                    ldsm_x4(r, a);
                    bh[jp*2][0] = r[0]; bh[jp*2][1] = r[1];
                    bh[jp*2+1][0] = r[2]; bh[jp*2+1][1] = r[3];
                    ldsm_x4(r, a + (WLo - WHo) * 4);
                    bl[jp*2][0] = r[0]; bl[jp*2][1] = r[1];
                    bl[jp*2+1][0] = r[2]; bl[jp*2+1][1] = r[3];
                }
#pragma unroll
                for (int mi = 0; mi < 2; mi++) {
                    uint32_t ah[4], al[4];
                    uint32_t a = sbase + (HHo + s * 1536 + (wm + mi * 16 + arow) * 12 + ak2) * 4;
                    ldsm_x4(ah, a);
                    ldsm_x4(al, a + (HLo - HHo) * 4);
#pragma unroll
                    for (int j = 0; j < 6; j++) {
                        mma_bf16(acc[mi][j], ah, bh[j]);
                        mma_bf16(acc[mi][j], al, bh[j]);
                        mma_bf16(acc[mi][j], ah, bl[j]);
                    }
                }
            }
#pragma unroll
            for (int mi = 0; mi < 2; mi++) {
                int r = wm + mi * 16 + gid;
#pragma unroll
                for (int j = 0; j < 6; j++) {
                    int col = c0 + wn + j * 8 + tig * 2;
                    float* p0 = part + (((size_t)ks * 2 + d) * B + r) * G3 + col;
                    float* p1 = part + (((size_t)ks * 2 + d) * B + r + 8) * G3 + col;
                    *(float2*)p0 = make_float2(acc[mi][j][0], acc[mi][j][1]);
                    *(float2*)p1 = make_float2(acc[mi][j][2], acc[mi][j][3]);
                }
            }
        }
        grid_sync(bar, NCTA, &gen);

        const int n0e = cnt0 * H2;
        const int total = n0e + cnt1 * H2;
        for (int it = cta * 256 + tid; it < total; it += nth) {
            int dd = (it >= n0e);
            int loc = dd ? (it - n0e) : it;
            int rr = loc / H2, j = (loc % H2) * 2;
            int te = dd ? (T - 1 - t) : t;
            int bo = perm[rr];
            float2 hold = *(const float2*)&hbuf[((size_t)dd * B + rr) * H + j];
            float2 hpr = make_float2(0.f, 0.f);
            float2 hpz = make_float2(0.f, 0.f);
            float2 hpn = make_float2(0.f, 0.f);
#pragma unroll
            for (int s = 0; s < KS; s++) {
                const float* pb = part + (((size_t)s * 2 + dd) * B + rr) * G3;
                float2 v;
                v = *(const float2*)(pb + j);         hpr.x += v.x; hpr.y += v.y;
                v = *(const float2*)(pb + H + j);     hpz.x += v.x; hpz.y += v.y;
                v = *(const float2*)(pb + 2 * H + j); hpn.x += v.x; hpn.y += v.y;
            }
            const float* bb = b_hh + (size_t)dd * G3;
            float2 br = *(const float2*)(bb + j);
            float2 bz = *(const float2*)(bb + H + j);
            float2 bn = *(const float2*)(bb + 2 * H + j);
            const float* xr = xp + ((size_t)bo * T + te) * (2 * G3) + (size_t)dd * G3;
            float2 xrv = *(const float2*)(xr + j);
            float2 xzv = *(const float2*)(xr + H + j);
            float2 xnv = *(const float2*)(xr + 2 * H + j);
            float rg0 = fast_sigmoid(xrv.x + hpr.x + br.x);
            float rg1 = fast_sigmoid(xrv.y + hpr.y + br.y);
            float zg0 = fast_sigmoid(xzv.x + hpz.x + bz.x);
            float zg1 = fast_sigmoid(xzv.y + hpz.y + bz.y);
            float ng0 = fast_tanh(xnv.x + rg0 * (hpn.x + bn.x));
            float ng1 = fast_tanh(xnv.y + rg1 * (hpn.y + bn.y));
            float2 hnew = make_float2((1.f - zg0) * ng0 + zg0 * hold.x,
                                      (1.f - zg1) * ng1 + zg1 * hold.y);
            *(float2*)&hbuf[((size_t)dd * B + rr) * H + j] = hnew;
            *(float2*)&out[((size_t)bo * T + te) * (2 * H) + dd * H + j] = hnew;
        }
        grid_sync(bar, NCTA, &gen);
    }
}

// ---------------- segment means ----------------
__global__ __launch_bounds__(256) void seg_mean_kernel(
    const float* __restrict__ vf, const float* __restrict__ loc,
    const int* __restrict__ v_len,
    float* __restrict__ lmean, float* __restrict__ rmean, float* __restrict__ cat)
{
    const int b = blockIdx.x;
    const int col = blockIdx.y * 256 + threadIdx.x;
    const int vl = v_len[b];
    const float scale = (float)(vl - 1);
    const float l0 = loc[b * 2], l1 = loc[b * 2 + 1];
    const int cond = (l0 <= l1);
    const float lhi = cond ? l0 : 0.f;
    const float rlo = cond ? l1 : 1.f;
    const int lend   = (int)floorf(lhi * scale);
    const int rstart = (int)floorf(rlo * scale);
    const int rend   = vl - 1;
    const int ok_l = (0 <= lend);
    const int ok_r = (rstart <= rend);

    float ls = 0.f, rs = 0.f, gs = 0.f;
    for (int t = 0; t < vl; t++) {
        float v = vf[((size_t)b * TV + t) * 1024 + col];
        gs += v;
        if (ok_l && t <= lend) ls += v;
        if (ok_r && t >= rstart) rs += v;
    }
    float lcnt = ok_l ? (float)(lend + 1) : 1.f;
    float rcnt = ok_r ? (float)(rend - rstart + 1) : 1.f;
    if (lcnt < 1.f) lcnt = 1.f;
    if (rcnt < 1.f) rcnt = 1.f;
    lmean[b * 1024 + col] = ls / lcnt;
    rmean[b * 1024 + col] = rs / rcnt;
    cat[(size_t)b * NCAT + 512 + col] = gs / (float)vl;
}

// ---------------- gather sen_fea ----------------
__global__ void gather_senfea(const float* __restrict__ words,
                              const int* __restrict__ lens,
                              float* __restrict__ out_sf, float* __restrict__ cat)
{
    const int b = blockIdx.x;
    const int t = lens[b] - 1;
    for (int c = threadIdx.x; c < 2 * SHID; c += blockDim.x) {
        float v = words[((size_t)b * TS + t) * (2 * SHID) + c];
        out_sf[(size_t)b * (2 * SHID) + c] = v;
        cat[(size_t)b * NCAT + c] = v;
    }
}

// ---------------- small GEMM with epilogue ----------------
__global__ __launch_bounds__(256) void gemm_small(
    const float* __restrict__ A, const float* __restrict__ W,
    const float* __restrict__ bias, const float* __restrict__ mul, int mulLd,
    float* __restrict__ C, int ldC, int M, int N, int K, int relu)
{
    const int n0 = blockIdx.x * 32, m0 = blockIdx.y * 32;
    __shared__ __align__(16) float As[32][34];
    __shared__ __align__(16) float Wsm[32][34];
    const int tid = threadIdx.x, ty = tid / 16, tx = tid % 16;
    float acc[2][2] = {{0.f, 0.f}, {0.f, 0.f}};

    for (int k0 = 0; k0 < K; k0 += 32) {
        for (int e = tid; e < 1024; e += 256) {
            int r = e / 32, k = e % 32;
            int kg = k0 + k;
            As[k][r]  = (kg < K) ? A[(size_t)(m0 + r) * K + kg] : 0.f;
            Wsm[k][r] = (kg < K) ? W[(size_t)(n0 + r) * K + kg] : 0.f;
        }
        __syncthreads();
#pragma unroll
        for (int k = 0; k < 32; k++) {
            float2 av = *(const float2*)&As[k][ty * 2];
            float2 wv = *(const float2*)&Wsm[k][tx * 2];
            acc[0][0] += av.x * wv.x;  acc[0][1] += av.x * wv.y;
            acc[1][0] += av.y * wv.x;  acc[1][1] += av.y * wv.y;
        }
        __syncthreads();
    }
#pragma unroll
    for (int i = 0; i < 2; i++) {
        int m = m0 + ty * 2 + i;
#pragma unroll
        for (int j = 0; j < 2; j++) {
            int n = n0 + tx * 2 + j;
            float v = acc[i][j] + bias[n];
            if (mul) v *= mul[(size_t)m * mulLd + n];
            if (relu) v = fmaxf(v, 0.f);
            C[(size_t)m * ldC + n] = v;
        }
    }
}

// ---------------- launch ----------------
extern "C" void kernel_launch(void* const* d_in, const int* in_sizes, int n_in,
                              void* d_out, int out_size)
{
    const float* gv     = (const float*)d_in[1];
    const float* sen    = (const float*)d_in[2];
    const float* loc    = (const float*)d_in[5];
    const int*   lens   = (const int*)  d_in[6];
    const int*   v_len  = (const int*)  d_in[7];
    const float* v_w_ih = (const float*)d_in[8];
    const float* v_w_hh = (const float*)d_in[9];
    const float* v_b_ih = (const float*)d_in[10];
    const float* v_b_hh = (const float*)d_in[11];
    const float* s_w_ih = (const float*)d_in[12];
    const float* s_w_hh = (const float*)d_in[13];
    const float* s_b_ih = (const float*)d_in[14];
    const float* s_b_hh = (const float*)d_in[15];
    const float* fc1_w  = (const float*)d_in[16];
    const float* fc1_b  = (const float*)d_in[17];
    const float* fc2_w  = (const float*)d_in[18];
    const float* fc2_b  = (const float*)d_in[19];
    const float* fc3_w  = (const float*)d_in[20];
    const float* fc3_b  = (const float*)d_in[21];
    const float* fc4_w  = (const float*)d_in[22];
    const float* fc4_b  = (const float*)d_in[23];

    float* out    = (float*)d_out;
    float* out_vf = out;
    float* out_sf = out + VF_ELEMS;
    float* out_ft = out + VF_ELEMS + SF_ELEMS;

    float *xp_v, *xp_s, *h_v, *h_s, *part_v, *part_s, *words;
    float *lmean, *rmean, *cat, *sproj;
    int *perm_v, *lenp_v, *perm_s, *lenp_s, *cnt_v, *cnt_s;
    int *ridx_v, *ridx_s, *nv;
    unsigned* bar;
    cudaGetSymbolAddress((void**)&xp_v,   g_xp_v);
    cudaGetSymbolAddress((void**)&xp_s,   g_xp_s);
    cudaGetSymbolAddress((void**)&h_v,    g_h_v);
    cudaGetSymbolAddress((void**)&h_s,    g_h_s);
    cudaGetSymbolAddress((void**)&part_v, g_part_v);
    cudaGetSymbolAddress((void**)&part_s, g_part_s);
    cudaGetSymbolAddress((void**)&words,  g_words);
    cudaGetSymbolAddress((void**)&lmean,  g_lmean);
    cudaGetSymbolAddress((void**)&rmean,  g_rmean);
    cudaGetSymbolAddress((void**)&cat,    g_cat);
    cudaGetSymbolAddress((void**)&sproj,  g_sproj);
    cudaGetSymbolAddress((void**)&perm_v, g_perm_v);
    cudaGetSymbolAddress((void**)&lenp_v, g_lenp_v);
    cudaGetSymbolAddress((void**)&perm_s, g_perm_s);
    cudaGetSymbolAddress((void**)&lenp_s, g_lenp_s);
    cudaGetSymbolAddress((void**)&cnt_v,  g_cnt_v);
    cudaGetSymbolAddress((void**)&cnt_s,  g_cnt_s);
    cudaGetSymbolAddress((void**)&ridx_v, g_ridx_v);
    cudaGetSymbolAddress((void**)&ridx_s, g_ridx_s);
    cudaGetSymbolAddress((void**)&nv,     g_nv);
    cudaGetSymbolAddress((void**)&bar,    g_bar);

    cudaFuncSetAttribute(gru_persistent<512, 1536, 256, 16, 8>,
                         cudaFuncAttributeMaxDynamicSharedMemorySize, GRU_SMEM);
    cudaFuncSetAttribute(gru_persistent<256, 768, 40, 8, 4>,
                         cudaFuncAttributeMaxDynamicSharedMemorySize, GRU_SMEM);
    cudaFuncSetAttribute(gemm_bf16x3,
                         cudaFuncAttributeMaxDynamicSharedMemorySize, GEMM_SMEM);

    // 1. init: sort + counts + compacted row lists + zero h + zero visual out
    sort_init_kernel<<<1, 128>>>(v_len, lens, perm_v, lenp_v, perm_s, lenp_s,
                                 cnt_v, cnt_s, ridx_v, ridx_s, nv, bar);
    zero_h_kernel<<<(2*B*VHID + 255) / 256, 256>>>(h_v, h_s);
    zero_out_kernel<<<(int)(VF_ELEMS/4 + 255) / 256, 256>>>((float4*)out_vf,
                                                            (int)(VF_ELEMS/4));

    // 2. input projections (3xBF16, row-compacted)
    gemm_bf16x3<<<dim3(3072/128, (B*TV)/128), 256, GEMM_SMEM>>>(
        gv,  v_w_ih, v_b_ih, xp_v, ridx_v, nv,     3072, VIN);
    gemm_bf16x3<<<dim3(1536/128, (B*TS)/128), 256, GEMM_SMEM>>>(
        sen, s_w_ih, s_b_ih, xp_s, ridx_s, nv + 1, 1536, SIN);

    // 3. persistent visual GRU (bf16x3 LDSM phase1)
    gru_persistent<512, 1536, 256, 16, 8><<<256, 256, GRU_SMEM>>>(
        xp_v, v_w_hh, v_b_hh, h_v, part_v, out_vf, perm_v, cnt_v, bar);

    // 4. persistent sentence GRU
    gru_persistent<256, 768, 40, 8, 4><<<64, 256, GRU_SMEM>>>(
        xp_s, s_w_hh, s_b_hh, h_s, part_s, words, perm_s, cnt_s, bar + 2);

    // 5. sen_fea gather
    gather_senfea<<<B, 256>>>(words, lens, out_sf, cat);

    // 6. segment means + global mean
    seg_mean_kernel<<<dim3(B, 4), 256>>>(out_vf, loc, v_len, lmean, rmean, cat);

    // 7. FC stack
    gemm_small<<<dim3(LCROSS/32, B/32), 256>>>(out_sf, fc2_w, fc2_b, nullptr, 0,
                                               sproj, LCROSS, B, LCROSS, 2*SHID, 0);
    gemm_small<<<dim3(LCROSS/32, B/32), 256>>>(lmean, fc1_w, fc1_b, sproj, LCROSS,
                                               cat + 1536, NCAT, B, LCROSS, 2*VHID, 1);
    gemm_small<<<dim3(LCROSS/32, B/32), 256>>>(rmean, fc1_w, fc1_b, sproj, LCROSS,
                                               cat + 2048, NCAT, B, LCROSS, 2*VHID, 1);
    gemm_small<<<dim3(NLOC/32, B/32), 256>>>(loc, fc3_w, fc3_b, nullptr, 0,
                                             cat + 2560, NCAT, B, NLOC, 2, 1);
    gemm_small<<<dim3(NFEAT/32, B/32), 256>>>(cat, fc4_w, fc4_b, nullptr, 0,
                                              out_ft, NFEAT, B, NFEAT, NCAT, 1);
}